// round 12
// baseline (speedup 1.0000x reference)
#include <cuda_runtime.h>
#include <math.h>
#include <stdint.h>

// Problem constants
#define NA   8      // agents
#define NDm  16     // N_DUMMY (timesteps)
#define Bb_  1024   // batch
#define Pp_  128    // plan
#define TP   256    // 2*P
#define Hh   256    // hidden
#define H3   768    // 3*H
#define H2   512    // 2*H
#define NC   16     // chains = agents * 2 dirs
#define ROWS 16384  // NDm * Bb_

// ---------------- scratch (device globals; no allocation allowed) -------------
__device__ float g_xg[NC * ROWS * TP];        // gathered inputs (tf32-rounded)
__device__ float g_gi[(long)NC * ROWS * H3];  // input projections
__device__ float g_outf[NA * ROWS * Hh];      // forward GRU outputs
__device__ float g_outb[NA * ROWS * Hh];      // backward GRU outputs
__device__ float g_scln[NA * ROWS * H2];      // scattered + LN (tf32-rounded)
__device__ float g_h1[NA * ROWS * Hh];        // MLP hidden
__device__ float g_h[NC * Bb_ * Hh];          // GRU hidden state (fp32)
__device__ float g_hr0[NC * Bb_ * Hh];        // tf32-rounded h, parity 0
__device__ float g_hr1[NC * Bb_ * Hh];        // tf32-rounded h, parity 1
__device__ float g_wit[(long)NC * H3 * TP];   // pre-rounded Wi per chain
__device__ float g_wht[NC * H3 * Hh];         // pre-rounded, chunk96-permuted Wh
__device__ float g_w1t[NA * Hh * H2];         // pre-rounded W1
__device__ int   g_fwd[ROWS], g_bwd[ROWS], g_scat[ROWS];
__device__ int   g_Pmask[ROWS], g_Ppm[ROWS];
__device__ int   g_seq[Bb_], g_empty[Bb_];
__device__ int   g_anyc[Bb_ * NA], g_anyp[Bb_ * NA];
__device__ unsigned char g_mreal[NA * Bb_];

__device__ __forceinline__ uint32_t f2tf32(float f) {
    uint32_t u;
    asm("cvt.rna.tf32.f32 %0, %1;" : "=r"(u) : "f"(f));
    return u;
}
__device__ __forceinline__ float roundtf(float f) {
    return __uint_as_float(f2tf32(f));
}

// ---------------- K1: per-(b,n) nonzero row flags ----------------------------
__global__ void __launch_bounds__(256) k_rowflags(
    const float* __restrict__ comm_plans,
    const float* __restrict__ plans,
    int* __restrict__ anyc, int* __restrict__ anyp)
{
    int warp = (blockIdx.x * blockDim.x + threadIdx.x) >> 5;
    int lane = threadIdx.x & 31;
    if (warp >= Bb_ * NA) return;
    float4 c4 = *reinterpret_cast<const float4*>(&comm_plans[(long)warp * Pp_ + lane * 4]);
    bool nzc = (c4.x != 0.f) || (c4.y != 0.f) || (c4.z != 0.f) || (c4.w != 0.f);
    unsigned mc = __ballot_sync(0xffffffffu, nzc);
    float4 p4 = *reinterpret_cast<const float4*>(&plans[(long)warp * Pp_ + lane * 4]);
    bool nzp = (p4.x != 0.f) || (p4.y != 0.f) || (p4.z != 0.f) || (p4.w != 0.f);
    unsigned mp = __ballot_sync(0xffffffffu, nzp);
    if (lane == 0) { anyc[warp] = (mc != 0u); anyp[warp] = (mp != 0u); }
}

// ---------------- K2: empty[b], mask_real[n][b] ------------------------------
__global__ void __launch_bounds__(256) k_maskreal(
    const int* __restrict__ anyc, const int* __restrict__ anyp,
    int* __restrict__ empty, unsigned char* __restrict__ mreal)
{
    int b = blockIdx.x * blockDim.x + threadIdx.x;
    if (b >= Bb_) return;
    int any = 0, ac[NA];
    #pragma unroll
    for (int n = 0; n < NA; n++) { ac[n] = anyc[b * NA + n]; any |= ac[n]; }
    int e = !any;
    empty[b] = e;
    #pragma unroll
    for (int n = 0; n < NA; n++)
        mreal[n * Bb_ + b] = e ? (unsigned char)anyp[b * NA + n] : (unsigned char)ac[n];
}

// ---------------- K3: packing index maps (single block) ----------------------
__global__ void __launch_bounds__(1024) k_indices(
    const unsigned char* __restrict__ mreal,
    int* __restrict__ seq_len,
    int* __restrict__ fwd_src, int* __restrict__ bwd_src,
    int* __restrict__ scat_src,
    int* __restrict__ Pmask, int* __restrict__ Ppm)
{
    int tid = threadIdx.x;            // 1024 threads
    {
        int b = tid, s = NDm - NA;
        #pragma unroll
        for (int t = 0; t < NA; t++) s += mreal[t * Bb_ + b];
        seq_len[b] = s;
    }
    __syncthreads();

    int base_j = tid * 16;
    unsigned m_bits = 0, p_bits = 0;
    int cm = 0, cp = 0;
    for (int r = 0; r < 16; r++) {
        int j = base_j + r;
        int t = j >> 10, b = j & 1023;
        int m = (t < NA) ? (int)mreal[j] : 1;
        int p = (t < seq_len[b]) ? 1 : 0;
        if (m) { m_bits |= 1u << r; cm++; }
        if (p) { p_bits |= 1u << r; cp++; }
    }
    __shared__ int wm[32], wp[32], tot;
    int lane = tid & 31, wid = tid >> 5;
    int sm = cm, sp = cp;
    #pragma unroll
    for (int o = 1; o < 32; o <<= 1) {
        int v = __shfl_up_sync(0xffffffffu, sm, o); if (lane >= o) sm += v;
        v     = __shfl_up_sync(0xffffffffu, sp, o); if (lane >= o) sp += v;
    }
    if (lane == 31) { wm[wid] = sm; wp[wid] = sp; }
    __syncthreads();
    if (wid == 0) {
        int a = wm[lane], c = wp[lane];
        #pragma unroll
        for (int o = 1; o < 32; o <<= 1) {
            int v = __shfl_up_sync(0xffffffffu, a, o); if (lane >= o) a += v;
            v     = __shfl_up_sync(0xffffffffu, c, o); if (lane >= o) c += v;
        }
        wm[lane] = a; wp[lane] = c;
        if (lane == 31) tot = a;
    }
    __syncthreads();
    int basem = sm - cm + (wid ? wm[wid - 1] : 0);
    int basep = sp - cp + (wid ? wp[wid - 1] : 0);
    int Ktot = tot;

    int km = basem, kp = basep;
    for (int r = 0; r < 16; r++) {
        int j = base_j + r;
        fwd_src[j] = -1;
        if (m_bits & (1u << r)) { Pmask[km] = j; scat_src[j] = km; km++; }
        else scat_src[j] = -1;
        if (p_bits & (1u << r)) { Ppm[kp] = j; kp++; }
    }
    __syncthreads();
    for (int k = tid; k < Ktot; k += 1024) fwd_src[Ppm[k]] = Pmask[k];
    __syncthreads();
    for (int r = 0; r < 16; r++) {
        int j = base_j + r;
        int t = j >> 10, b = j & 1023;
        int sl = seq_len[b];
        bwd_src[j] = (t < sl) ? fwd_src[(sl - 1 - t) * Bb_ + b] : -1;
    }
}

// ---------------- K4: init h (fp32 + tf32-rounded copy) ----------------------
__global__ void __launch_bounds__(256) k_prep_h0(
    const float* __restrict__ src, float* __restrict__ h, float* __restrict__ hr, int n)
{
    int i = blockIdx.x * blockDim.x + threadIdx.x;
    if (i < n) {
        float v = src[i];
        h[i] = v;
        hr[i] = roundtf(v);
    }
}

// ---------------- K4b/c/d: pre-round weights ---------------------------------
__global__ void __launch_bounds__(256) k_prep_wi(
    const float* __restrict__ Wi_f, const float* __restrict__ Wi_b,
    float* __restrict__ wit)
{
    long idx = (long)blockIdx.x * 256 + threadIdx.x;
    if (idx >= (long)NC * H3 * TP) return;
    int k = (int)(idx % TP);
    long r2 = idx / TP;
    int n = (int)(r2 % H3);
    int z = (int)(r2 / H3);
    int i = z >> 1, d = z & 1;
    const float* src = d ? Wi_b : Wi_f;
    wit[idx] = roundtf(src[((long)i * H3 + n) * TP + k]);
}

// Wh permuted for chunk=96: new row n_new (0..767) within a chain:
//   chunk c = n_new/96 (8 chunks), rem = n_new%96, group g = rem/24 (4 groups),
//   gate = (rem%24)/8, j = rem%8;  orig row = gate*Hh + c*32 + g*8 + j
__global__ void __launch_bounds__(256) k_prep_wh(
    const float* __restrict__ Wh_f, const float* __restrict__ Wh_b,
    float* __restrict__ wht)
{
    long idx = (long)blockIdx.x * 256 + threadIdx.x;
    if (idx >= (long)NC * H3 * Hh) return;
    int k = (int)(idx % Hh);
    long r2 = idx / Hh;
    int nn = (int)(r2 % H3);
    int z = (int)(r2 / H3);
    int i = z >> 1, d = z & 1;
    int c    = nn / 96;
    int rem  = nn % 96;
    int g    = rem / 24;
    int gate = (rem % 24) / 8;
    int j    = rem % 8;
    int orig = gate * Hh + c * 32 + g * 8 + j;
    const float* src = d ? Wh_b : Wh_f;
    wht[idx] = roundtf(src[((long)i * H3 + orig) * Hh + k]);
}

__global__ void __launch_bounds__(256) k_prep_w1(
    const float* __restrict__ W1, float* __restrict__ w1t)
{
    long idx = (long)blockIdx.x * 256 + threadIdx.x;
    if (idx >= (long)NA * Hh * H2) return;
    w1t[idx] = roundtf(W1[idx]);
}

// ---------------- K5: gather x rows per chain (writes tf32-rounded) ----------
__global__ void __launch_bounds__(64) k_gather(
    const float* __restrict__ plans, const float* __restrict__ comm_plans,
    const float* __restrict__ dummy,
    const int* __restrict__ fwd_src, const int* __restrict__ bwd_src,
    const int* __restrict__ empty, float* __restrict__ xg)
{
    int j = blockIdx.x;           // 0..16383 packed row (t*B+b)
    int z = blockIdx.y;           // chain
    int c = threadIdx.x * 4;      // 64 threads * 4 = 256 feats
    int i = z >> 1, d = z & 1;
    int src = (d ? bwd_src : fwd_src)[j];
    float4 v = make_float4(0.f, 0.f, 0.f, 0.f);
    if (src >= 0) {
        int ts = src >> 10, bs = src & 1023;
        if (ts < NA) {
            if (c < Pp_) {
                v = *reinterpret_cast<const float4*>(&plans[((long)bs * NA + i) * Pp_ + c]);
            } else {
                const float* sp = empty[bs] ? plans : comm_plans;
                v = *reinterpret_cast<const float4*>(&sp[((long)bs * NA + ts) * Pp_ + (c - Pp_)]);
            }
        } else {
            v = *reinterpret_cast<const float4*>(
                &dummy[(((long)i * (NDm - NA) + (ts - NA)) * Bb_ + bs) * TP + c]);
        }
    }
    v.x = roundtf(v.x); v.y = roundtf(v.y); v.z = roundtf(v.z); v.w = roundtf(v.w);
    *reinterpret_cast<float4*>(&xg[((long)z * ROWS + j) * TP + c]) = v;
}

// ---------------- tf32 tensor-core NT GEMM, pre-rounded operands -------------
#define BM 128
#define BN 128
#define BKq 16
#define SSTR 20
#define GSTG_W ((BM + BN) * SSTR)     // 5120 words per stage
#define GSMEM_BYTES (3 * GSTG_W * 4)  // 61440

__device__ __forceinline__ void cpa16(uint32_t dst, const float* src) {
    asm volatile("cp.async.ca.shared.global [%0], [%1], 16;" :: "r"(dst), "l"(src));
}

__global__ void __launch_bounds__(256, 2) gemm_pre(
    const float* __restrict__ Abase, const float* __restrict__ Wbase,
    float* __restrict__ Cbase, const float* __restrict__ biasBase,
    int M, int N, int K,
    long sA, long sB, long sC, long sBias, int relu)
{
    extern __shared__ float dynsm[];
    int z = blockIdx.z;
    const float* A = Abase + (long)z * sA;
    const float* W = Wbase + (long)z * sB;
    float* C = Cbase + (long)z * sC;
    const float* bias = biasBase ? (biasBase + (long)z * sBias) : nullptr;

    int tid  = threadIdx.x;
    int lane = tid & 31;
    int warp = tid >> 5;
    int wm   = warp & 3;
    int wn   = warp >> 2;
    int m0   = blockIdx.x * BM;
    int n0   = blockIdx.y * BN;

    uint32_t smem_base = (uint32_t)__cvta_generic_to_shared((void*)dynsm);

    float acc[2][8][4];
    #pragma unroll
    for (int a = 0; a < 2; a++)
        #pragma unroll
        for (int b = 0; b < 8; b++)
            #pragma unroll
            for (int c = 0; c < 4; c++) acc[a][b][c] = 0.f;

    int lrow = tid >> 2;
    int lkq  = (tid & 3) * 4;

    auto load_stage = [&](int buf, int k0) {
        uint32_t sAa = smem_base + (buf * GSTG_W) * 4;
        uint32_t sBb = smem_base + (buf * GSTG_W + BM * SSTR) * 4;
        #pragma unroll
        for (int p = 0; p < 2; p++) {
            int row = lrow + p * 64;
            cpa16(sAa + (row * SSTR + lkq) * 4, &A[(long)(m0 + row) * K + k0 + lkq]);
            cpa16(sBb + (row * SSTR + lkq) * 4, &W[(long)(n0 + row) * K + k0 + lkq]);
        }
    };

    const int NSTG = K / BKq;
    load_stage(0, 0);
    asm volatile("cp.async.commit_group;");
    load_stage(1, BKq);
    asm volatile("cp.async.commit_group;");

    for (int s = 0; s < NSTG; s++) {
        if (s + 1 < NSTG) asm volatile("cp.async.wait_group 1;");
        else              asm volatile("cp.async.wait_group 0;");
        __syncthreads();
        if (s + 2 < NSTG) {
            load_stage((s + 2) % 3, (s + 2) * BKq);
            asm volatile("cp.async.commit_group;");
        }
        const uint32_t* Ash = reinterpret_cast<const uint32_t*>(dynsm + (s % 3) * GSTG_W);
        const uint32_t* Bsh = Ash + BM * SSTR;

        #pragma unroll
        for (int ks = 0; ks < BKq; ks += 8) {
            uint32_t afr[2][4], bfr[8][2];
            int ar = wm * 32 + (lane >> 2);
            int ac = ks + (lane & 3);
            #pragma unroll
            for (int mt = 0; mt < 2; mt++) {
                int r = ar + mt * 16;
                afr[mt][0] = Ash[r * SSTR + ac];
                afr[mt][1] = Ash[(r + 8) * SSTR + ac];
                afr[mt][2] = Ash[r * SSTR + ac + 4];
                afr[mt][3] = Ash[(r + 8) * SSTR + ac + 4];
            }
            int bn = wn * 64 + (lane >> 2);
            int bk = ks + (lane & 3);
            #pragma unroll
            for (int nt = 0; nt < 8; nt++) {
                int n = bn + nt * 8;
                bfr[nt][0] = Bsh[n * SSTR + bk];
                bfr[nt][1] = Bsh[n * SSTR + bk + 4];
            }
            #pragma unroll
            for (int mt = 0; mt < 2; mt++)
                #pragma unroll
                for (int nt = 0; nt < 8; nt++)
                    asm volatile(
                        "mma.sync.aligned.m16n8k8.row.col.f32.tf32.tf32.f32 "
                        "{%0,%1,%2,%3}, {%4,%5,%6,%7}, {%8,%9}, {%0,%1,%2,%3};"
                        : "+f"(acc[mt][nt][0]), "+f"(acc[mt][nt][1]),
                          "+f"(acc[mt][nt][2]), "+f"(acc[mt][nt][3])
                        : "r"(afr[mt][0]), "r"(afr[mt][1]), "r"(afr[mt][2]), "r"(afr[mt][3]),
                          "r"(bfr[nt][0]), "r"(bfr[nt][1]));
        }
    }

    #pragma unroll
    for (int mt = 0; mt < 2; mt++) {
        int r0 = m0 + wm * 32 + mt * 16 + (lane >> 2);
        #pragma unroll
        for (int nt = 0; nt < 8; nt++) {
            int cb = n0 + wn * 64 + nt * 8 + (lane & 3) * 2;
            float v0 = acc[mt][nt][0], v1 = acc[mt][nt][1];
            float v2 = acc[mt][nt][2], v3 = acc[mt][nt][3];
            if (bias) {
                float b0v = bias[cb], b1v = bias[cb + 1];
                v0 += b0v; v1 += b1v; v2 += b0v; v3 += b1v;
            }
            if (relu) {
                v0 = fmaxf(v0, 0.f); v1 = fmaxf(v1, 0.f);
                v2 = fmaxf(v2, 0.f); v3 = fmaxf(v3, 0.f);
            }
            *reinterpret_cast<float2*>(&C[(long)r0 * N + cb])       = make_float2(v0, v1);
            *reinterpret_cast<float2*>(&C[(long)(r0 + 8) * N + cb]) = make_float2(v2, v3);
        }
    }
}

// ---------------- fused recurrence step, geometry v2 --------------------------
// CTA = (128 batch rows, one 96-col permuted chunk = 32 hidden cols, chain z).
// 8 warps = 4M x 2N; N-warp owns 48 cols = 2 complete (r,z,n) triple-groups.
// acc = 48 regs -> 2 CTAs/SM. Gates in registers; no gh tensor.
#define RBM2 128
#define RCH  96
#define RSTG_W ((RBM2 + RCH) * SSTR)    // 4480 words per stage
#define RSMEM_BYTES (3 * RSTG_W * 4)    // 53760

__global__ void __launch_bounds__(256, 2) k_rec_step(
    const float* __restrict__ hr_in,   // [NC][1024][256] rounded (read)
    float* __restrict__ hr_out,        // [NC][1024][256] rounded (write)
    float* __restrict__ h,             // [NC][1024][256] fp32
    const float* __restrict__ wht,     // chunk96-permuted [NC][768][256]
    const float* __restrict__ gi,      // [NC][ROWS][768] gate-blocked
    float* __restrict__ outf, float* __restrict__ outb,
    const int* __restrict__ seq_len, int t)
{
    extern __shared__ float dynsm[];
    int z  = blockIdx.z;
    int m0 = blockIdx.x * RBM2;
    int c  = blockIdx.y;               // chunk 0..7 -> hidden cols [32c,32c+32)

    const float* A = hr_in + (long)z * Bb_ * Hh;
    const float* W = wht + ((long)z * H3 + c * RCH) * Hh;

    int tid  = threadIdx.x;
    int lane = tid & 31;
    int warp = tid >> 5;
    int wm   = warp & 3;               // 4 M-warps x 32 rows
    int wn   = warp >> 2;              // 2 N-warps x 48 cols

    uint32_t smem_base = (uint32_t)__cvta_generic_to_shared((void*)dynsm);

    float acc[2][6][4];
    #pragma unroll
    for (int a = 0; a < 2; a++)
        #pragma unroll
        for (int b = 0; b < 6; b++)
            #pragma unroll
            for (int q = 0; q < 4; q++) acc[a][b][q] = 0.f;

    int lrow = tid >> 2;
    int lkq  = (tid & 3) * 4;

    auto load_stage = [&](int buf, int k0) {
        uint32_t sAa = smem_base + (buf * RSTG_W) * 4;
        uint32_t sBb = smem_base + (buf * RSTG_W + RBM2 * SSTR) * 4;
        #pragma unroll
        for (int p = 0; p < 2; p++) {   // A: 128 rows x 16 cols
            int row = lrow + p * 64;
            cpa16(sAa + (row * SSTR + lkq) * 4, &A[(long)(m0 + row) * Hh + k0 + lkq]);
        }
        if (tid < 128) {                // B: 96 rows x 16 cols (384 quads)
            #pragma unroll
            for (int p = 0; p < 3; p++) {
                int idx = tid + p * 128;
                int row = idx >> 2, kq = (idx & 3) * 4;
                cpa16(sBb + (row * SSTR + kq) * 4, &W[(long)row * Hh + k0 + kq]);
            }
        }
    };

    const int NSTG = Hh / BKq;   // 16
    load_stage(0, 0);
    asm volatile("cp.async.commit_group;");
    load_stage(1, BKq);
    asm volatile("cp.async.commit_group;");

    for (int s = 0; s < NSTG; s++) {
        if (s + 1 < NSTG) asm volatile("cp.async.wait_group 1;");
        else              asm volatile("cp.async.wait_group 0;");
        __syncthreads();
        if (s + 2 < NSTG) {
            load_stage((s + 2) % 3, (s + 2) * BKq);
            asm volatile("cp.async.commit_group;");
        }
        const uint32_t* Ash = reinterpret_cast<const uint32_t*>(dynsm + (s % 3) * RSTG_W);
        const uint32_t* Bsh = Ash + RBM2 * SSTR;

        #pragma unroll
        for (int ks = 0; ks < BKq; ks += 8) {
            uint32_t afr[2][4], bfr[6][2];
            int ar = wm * 32 + (lane >> 2);
            int ac = ks + (lane & 3);
            #pragma unroll
            for (int mt = 0; mt < 2; mt++) {
                int r = ar + mt * 16;
                afr[mt][0] = Ash[r * SSTR + ac];
                afr[mt][1] = Ash[(r + 8) * SSTR + ac];
                afr[mt][2] = Ash[r * SSTR + ac + 4];
                afr[mt][3] = Ash[(r + 8) * SSTR + ac + 4];
            }
            int bn = wn * 48 + (lane >> 2);
            int bk = ks + (lane & 3);
            #pragma unroll
            for (int nt = 0; nt < 6; nt++) {
                int n = bn + nt * 8;
                bfr[nt][0] = Bsh[n * SSTR + bk];
                bfr[nt][1] = Bsh[n * SSTR + bk + 4];
            }
            #pragma unroll
            for (int mt = 0; mt < 2; mt++)
                #pragma unroll
                for (int nt = 0; nt < 6; nt++)
                    asm volatile(
                        "mma.sync.aligned.m16n8k8.row.col.f32.tf32.tf32.f32 "
                        "{%0,%1,%2,%3}, {%4,%5,%6,%7}, {%8,%9}, {%0,%1,%2,%3};"
                        : "+f"(acc[mt][nt][0]), "+f"(acc[mt][nt][1]),
                          "+f"(acc[mt][nt][2]), "+f"(acc[mt][nt][3])
                        : "r"(afr[mt][0]), "r"(afr[mt][1]), "r"(afr[mt][2]), "r"(afr[mt][3]),
                          "r"(bfr[nt][0]), "r"(bfr[nt][1]));
        }
    }

    // gate phase — warp wn owns groups {2wn, 2wn+1}; nt = gl*3 + gate
    int ii = z >> 1, d = z & 1;
    float* outp = d ? outb : outf;
    long gi_t  = ((long)z * ROWS + (long)t * Bb_ + m0) * H3;
    long out_t = ((long)ii * ROWS + (long)t * Bb_ + m0) * Hh;
    float* hz  = h + ((long)z * Bb_ + m0) * Hh;
    float* hro = hr_out + ((long)z * Bb_ + m0) * Hh;

    #pragma unroll
    for (int mt = 0; mt < 2; mt++) {
        #pragma unroll
        for (int rr = 0; rr < 2; rr++) {
            int row = wm * 32 + mt * 16 + rr * 8 + (lane >> 2);
            int b = m0 + row;
            bool v = t < __ldg(&seq_len[b]);
            long girow = gi_t + (long)row * H3;
            #pragma unroll
            for (int gl = 0; gl < 2; gl++) {
                int g = 2 * wn + gl;
                #pragma unroll
                for (int cc = 0; cc < 2; cc++) {
                    int hc = c * 32 + g * 8 + (lane & 3) * 2 + cc;
                    float gir = __ldg(&gi[girow + hc]);
                    float giz = __ldg(&gi[girow + Hh + hc]);
                    float gin = __ldg(&gi[girow + 2 * Hh + hc]);
                    int q = rr * 2 + cc;
                    float ghr = acc[mt][gl * 3 + 0][q];
                    float ghz = acc[mt][gl * 3 + 1][q];
                    float ghn = acc[mt][gl * 3 + 2][q];
                    float hp = hz[(long)row * Hh + hc];
                    float r  = 1.f / (1.f + expf(-(gir + ghr)));
                    float zz = 1.f / (1.f + expf(-(giz + ghz)));
                    float nn = tanhf(gin + r * ghn);
                    float hn = (1.f - zz) * nn + zz * hp;
                    float hnew = v ? hn : hp;
                    hz[(long)row * Hh + hc]  = hnew;
                    hro[(long)row * Hh + hc] = roundtf(hnew);
                    outp[out_t + (long)row * Hh + hc] = v ? hn : 0.f;
                }
            }
        }
    }
}

// ---------------- K7: scatter + reverse + layernorm (writes rounded) ---------
__global__ void __launch_bounds__(128) k_scores_ln(
    const float* __restrict__ outf, const float* __restrict__ outb,
    const int* __restrict__ scat, const int* __restrict__ seq_len,
    const float* __restrict__ ln_g, const float* __restrict__ ln_b,
    float* __restrict__ scln)
{
    int j = blockIdx.x;          // row (t*B+b) in mask layout
    int i = blockIdx.y;          // agent
    int tid = threadIdx.x;       // 128 threads, 4 cols each
    __shared__ float s1[128], s2[128];
    float v0 = 0.f, v1 = 0.f, v2 = 0.f, v3 = 0.f;
    int k = scat[j];
    if (k >= 0) {
        int tp = k >> 10, bp = k & 1023;
        if (tid < 64) {
            float4 f = *reinterpret_cast<const float4*>(&outf[((long)i * ROWS + k) * Hh + tid * 4]);
            v0 = f.x; v1 = f.y; v2 = f.z; v3 = f.w;
        } else {
            int sl = seq_len[bp];
            if (tp < sl) {
                int rb = sl - 1 - tp;
                float4 f = *reinterpret_cast<const float4*>(
                    &outb[((long)i * ROWS + rb * Bb_ + bp) * Hh + (tid - 64) * 4]);
                v0 = f.x; v1 = f.y; v2 = f.z; v3 = f.w;
            }
        }
    }
    s1[tid] = v0 + v1 + v2 + v3;
    s2[tid] = v0 * v0 + v1 * v1 + v2 * v2 + v3 * v3;
    __syncthreads();
    for (int off = 64; off > 0; off >>= 1) {
        if (tid < off) { s1[tid] += s1[tid + off]; s2[tid] += s2[tid + off]; }
        __syncthreads();
    }
    float mu  = s1[0] * (1.f / H2);
    float var = s2[0] * (1.f / H2) - mu * mu;
    float rs  = rsqrtf(var + 1e-5f);
    int c = tid * 4;
    const float* g = &ln_g[i * H2 + c];
    const float* bt = &ln_b[i * H2 + c];
    float4 o;
    o.x = roundtf((v0 - mu) * rs * g[0] + bt[0]);
    o.y = roundtf((v1 - mu) * rs * g[1] + bt[1]);
    o.z = roundtf((v2 - mu) * rs * g[2] + bt[2]);
    o.w = roundtf((v3 - mu) * rs * g[3] + bt[3]);
    *reinterpret_cast<float4*>(&scln[((long)i * ROWS + j) * H2 + c]) = o;
}

// ---------------- K8: final 2-wide projection --------------------------------
__global__ void __launch_bounds__(256) k_w2out(
    const float* __restrict__ h1, const float* __restrict__ W2,
    const float* __restrict__ b2, float* __restrict__ out)
{
    int gw = (blockIdx.x * blockDim.x + threadIdx.x) >> 5;
    int lane = threadIdx.x & 31;
    if (gw >= NA * ROWS) return;
    int i = gw >> 14;
    int j = gw & 16383;
    const float* hr = &h1[((long)i * ROWS + j) * Hh];
    const float* w0 = &W2[(i * 2 + 0) * Hh];
    const float* w1 = &W2[(i * 2 + 1) * Hh];
    float a0 = 0.f, a1 = 0.f;
    #pragma unroll
    for (int q = 0; q < 8; q++) {
        float hv = hr[lane + q * 32];
        a0 = fmaf(hv, w0[lane + q * 32], a0);
        a1 = fmaf(hv, w1[lane + q * 32], a1);
    }
    #pragma unroll
    for (int o = 16; o > 0; o >>= 1) {
        a0 += __shfl_down_sync(0xffffffffu, a0, o);
        a1 += __shfl_down_sync(0xffffffffu, a1, o);
    }
    if (lane == 0) {
        int t = j >> 10, b = j & 1023;
        long base = (((long)i * NDm + t) * Bb_ + b) * 2;
        out[base + 0] = a0 + b2[i * 2 + 0];
        out[base + 1] = a1 + b2[i * 2 + 1];
    }
}

// ---------------- K9: copy final hidden states to output ---------------------
__global__ void __launch_bounds__(256) k_copy_hx(
    const float* __restrict__ h, float* __restrict__ out, int n)
{
    int i = blockIdx.x * blockDim.x + threadIdx.x;
    if (i < n) out[i] = h[i];
}

// ---------------- host orchestration -----------------------------------------
extern "C" void kernel_launch(void* const* d_in, const int* in_sizes, int n_in,
                              void* d_out, int out_size)
{
    const float* plans         = (const float*)d_in[0];
    const float* comm_plans    = (const float*)d_in[1];
    const float* coord_hiddens = (const float*)d_in[2];
    const float* dummy_noise   = (const float*)d_in[3];
    const float* Wi_f = (const float*)d_in[4];
    const float* Wh_f = (const float*)d_in[5];
    const float* Wi_b = (const float*)d_in[6];
    const float* Wh_b = (const float*)d_in[7];
    const float* ln_g = (const float*)d_in[8];
    const float* ln_b = (const float*)d_in[9];
    const float* W1   = (const float*)d_in[10];
    const float* b1   = (const float*)d_in[11];
    const float* W2   = (const float*)d_in[12];
    const float* b2   = (const float*)d_in[13];
    float* out = (float*)d_out;

    float *xg, *gi, *outf, *outb, *scln, *h1, *hst, *hr0, *hr1, *wit, *wht, *w1t;
    int *fwd, *bwd, *scat, *Pm, *Pp, *seq, *emp, *anyc, *anyp;
    unsigned char* mreal;
    cudaGetSymbolAddress((void**)&xg,   g_xg);
    cudaGetSymbolAddress((void**)&gi,   g_gi);
    cudaGetSymbolAddress((void**)&outf, g_outf);
    cudaGetSymbolAddress((void**)&outb, g_outb);
    cudaGetSymbolAddress((void**)&scln, g_scln);
    cudaGetSymbolAddress((void**)&h1,   g_h1);
    cudaGetSymbolAddress((void**)&hst,  g_h);
    cudaGetSymbolAddress((void**)&hr0,  g_hr0);
    cudaGetSymbolAddress((void**)&hr1,  g_hr1);
    cudaGetSymbolAddress((void**)&wit,  g_wit);
    cudaGetSymbolAddress((void**)&wht,  g_wht);
    cudaGetSymbolAddress((void**)&w1t,  g_w1t);
    cudaGetSymbolAddress((void**)&fwd,  g_fwd);
    cudaGetSymbolAddress((void**)&bwd,  g_bwd);
    cudaGetSymbolAddress((void**)&scat, g_scat);
    cudaGetSymbolAddress((void**)&Pm,   g_Pmask);
    cudaGetSymbolAddress((void**)&Pp,   g_Ppm);
    cudaGetSymbolAddress((void**)&seq,  g_seq);
    cudaGetSymbolAddress((void**)&emp,  g_empty);
    cudaGetSymbolAddress((void**)&anyc, g_anyc);
    cudaGetSymbolAddress((void**)&anyp, g_anyp);
    cudaGetSymbolAddress((void**)&mreal, g_mreal);

    cudaFuncSetAttribute(gemm_pre, cudaFuncAttributeMaxDynamicSharedMemorySize,
                         GSMEM_BYTES);
    cudaFuncSetAttribute(k_rec_step, cudaFuncAttributeMaxDynamicSharedMemorySize,
                         RSMEM_BYTES);

    // masks + packing indices
    k_rowflags<<<1024, 256>>>(comm_plans, plans, anyc, anyp);
    k_maskreal<<<4, 256>>>(anyc, anyp, emp, mreal);
    k_indices<<<1, 1024>>>(mreal, seq, fwd, bwd, scat, Pm, Pp);

    // init hidden + pre-round weights
    k_prep_h0<<<(NC * Bb_ * Hh + 255) / 256, 256>>>(coord_hiddens, hst, hr0, NC * Bb_ * Hh);
    k_prep_wi<<<(int)(((long)NC * H3 * TP + 255) / 256), 256>>>(Wi_f, Wi_b, wit);
    k_prep_wh<<<(int)(((long)NC * H3 * Hh + 255) / 256), 256>>>(Wh_f, Wh_b, wht);
    k_prep_w1<<<(int)(((long)NA * Hh * H2 + 255) / 256), 256>>>(W1, w1t);

    // gather inputs (rounded) and input projections
    k_gather<<<dim3(ROWS, NC), 64>>>(plans, comm_plans, dummy_noise, fwd, bwd, emp, xg);
    gemm_pre<<<dim3(ROWS / BM, H3 / BN, NC), 256, GSMEM_BYTES>>>(
        xg, wit, gi, nullptr,
        ROWS, H3, TP,
        (long)ROWS * TP, (long)H3 * TP, (long)ROWS * H3, 0, 0);

    // 16 fused recurrent steps (GEMM + gates in one kernel, no gh tensor)
    for (int t = 0; t < NDm; t++) {
        float* hin  = (t & 1) ? hr1 : hr0;
        float* hout = (t & 1) ? hr0 : hr1;
        k_rec_step<<<dim3(Bb_ / RBM2, H3 / RCH, NC), 256, RSMEM_BYTES>>>(
            hin, hout, hst, wht, gi, outf, outb, seq, t);
    }

    // scatter + reverse + layernorm (rounded output)
    k_scores_ln<<<dim3(ROWS, NA), 128>>>(outf, outb, scat, seq, ln_g, ln_b, scln);

    // MLP: h1 = relu(scln @ W1^T + b1)
    gemm_pre<<<dim3(ROWS / BM, Hh / BN, NA), 256, GSMEM_BYTES>>>(
        scln, w1t, h1, b1,
        ROWS, Hh, H2,
        (long)ROWS * H2, (long)Hh * H2, (long)ROWS * Hh, Hh, 1);

    // final projection -> coord_masks (N, ND, B, 2)
    k_w2out<<<(NA * ROWS * 32 + 255) / 256, 256>>>(h1, W2, b2, out);

    // coord_rnn_hxs (N, 2, B, H) appended after coord_masks
    int masks_elems = NA * NDm * Bb_ * 2;
    int hx_elems = NC * Bb_ * Hh;
    if (out_size >= masks_elems + hx_elems) {
        k_copy_hx<<<(hx_elems + 255) / 256, 256>>>(hst, out + masks_elems, hx_elems);
    }
}

// round 13
// speedup vs baseline: 1.3137x; 1.3137x over previous
#include <cuda_runtime.h>
#include <math.h>
#include <stdint.h>

// Problem constants
#define NA   8      // agents
#define NDm  16     // N_DUMMY (timesteps)
#define Bb_  1024   // batch
#define Pp_  128    // plan
#define TP   256    // 2*P
#define Hh   256    // hidden
#define H3   768    // 3*H
#define H2   512    // 2*H
#define NC   16     // chains = agents * 2 dirs
#define ROWS 16384  // NDm * Bb_

// ---------------- scratch (device globals; no allocation allowed) -------------
__device__ float g_xg[NC * ROWS * TP];        // gathered inputs (tf32-rounded)
__device__ float g_gi[(long)NC * ROWS * H3];  // input projections
__device__ float g_gh[NC * Bb_ * H3];         // per-step hidden projections
__device__ float g_outf[NA * ROWS * Hh];      // forward GRU outputs
__device__ float g_outb[NA * ROWS * Hh];      // backward GRU outputs
__device__ float g_scln[NA * ROWS * H2];      // scattered + LN (tf32-rounded)
__device__ float g_h1[NA * ROWS * Hh];        // MLP hidden
__device__ float g_h[NC * Bb_ * Hh];          // GRU hidden state (fp32)
__device__ float g_hr[NC * Bb_ * Hh];         // tf32-rounded shadow of h
__device__ float g_wit[(long)NC * H3 * TP];   // pre-rounded Wi per chain
__device__ float g_wht[NC * H3 * Hh];         // pre-rounded Wh per chain
__device__ float g_w1t[NA * Hh * H2];         // pre-rounded W1
__device__ int   g_fwd[ROWS], g_bwd[ROWS], g_scat[ROWS];
__device__ int   g_Pmask[ROWS], g_Ppm[ROWS];
__device__ int   g_seq[Bb_], g_empty[Bb_];
__device__ int   g_anyc[Bb_ * NA], g_anyp[Bb_ * NA];
__device__ unsigned char g_mreal[NA * Bb_];

__device__ __forceinline__ uint32_t f2tf32(float f) {
    uint32_t u;
    asm("cvt.rna.tf32.f32 %0, %1;" : "=r"(u) : "f"(f));
    return u;
}
__device__ __forceinline__ float roundtf(float f) {
    return __uint_as_float(f2tf32(f));
}

// ---------------- K1: per-(b,n) nonzero row flags ----------------------------
__global__ void __launch_bounds__(256) k_rowflags(
    const float* __restrict__ comm_plans,
    const float* __restrict__ plans,
    int* __restrict__ anyc, int* __restrict__ anyp)
{
    int warp = (blockIdx.x * blockDim.x + threadIdx.x) >> 5;
    int lane = threadIdx.x & 31;
    if (warp >= Bb_ * NA) return;
    float4 c4 = *reinterpret_cast<const float4*>(&comm_plans[(long)warp * Pp_ + lane * 4]);
    bool nzc = (c4.x != 0.f) || (c4.y != 0.f) || (c4.z != 0.f) || (c4.w != 0.f);
    unsigned mc = __ballot_sync(0xffffffffu, nzc);
    float4 p4 = *reinterpret_cast<const float4*>(&plans[(long)warp * Pp_ + lane * 4]);
    bool nzp = (p4.x != 0.f) || (p4.y != 0.f) || (p4.z != 0.f) || (p4.w != 0.f);
    unsigned mp = __ballot_sync(0xffffffffu, nzp);
    if (lane == 0) { anyc[warp] = (mc != 0u); anyp[warp] = (mp != 0u); }
}

// ---------------- K2: empty[b], mask_real[n][b] ------------------------------
__global__ void __launch_bounds__(256) k_maskreal(
    const int* __restrict__ anyc, const int* __restrict__ anyp,
    int* __restrict__ empty, unsigned char* __restrict__ mreal)
{
    int b = blockIdx.x * blockDim.x + threadIdx.x;
    if (b >= Bb_) return;
    int any = 0, ac[NA];
    #pragma unroll
    for (int n = 0; n < NA; n++) { ac[n] = anyc[b * NA + n]; any |= ac[n]; }
    int e = !any;
    empty[b] = e;
    #pragma unroll
    for (int n = 0; n < NA; n++)
        mreal[n * Bb_ + b] = e ? (unsigned char)anyp[b * NA + n] : (unsigned char)ac[n];
}

// ---------------- K3: packing index maps (single block) ----------------------
__global__ void __launch_bounds__(1024) k_indices(
    const unsigned char* __restrict__ mreal,
    int* __restrict__ seq_len,
    int* __restrict__ fwd_src, int* __restrict__ bwd_src,
    int* __restrict__ scat_src,
    int* __restrict__ Pmask, int* __restrict__ Ppm)
{
    int tid = threadIdx.x;            // 1024 threads
    {
        int b = tid, s = NDm - NA;
        #pragma unroll
        for (int t = 0; t < NA; t++) s += mreal[t * Bb_ + b];
        seq_len[b] = s;
    }
    __syncthreads();

    int base_j = tid * 16;
    unsigned m_bits = 0, p_bits = 0;
    int cm = 0, cp = 0;
    for (int r = 0; r < 16; r++) {
        int j = base_j + r;
        int t = j >> 10, b = j & 1023;
        int m = (t < NA) ? (int)mreal[j] : 1;
        int p = (t < seq_len[b]) ? 1 : 0;
        if (m) { m_bits |= 1u << r; cm++; }
        if (p) { p_bits |= 1u << r; cp++; }
    }
    __shared__ int wm[32], wp[32], tot;
    int lane = tid & 31, wid = tid >> 5;
    int sm = cm, sp = cp;
    #pragma unroll
    for (int o = 1; o < 32; o <<= 1) {
        int v = __shfl_up_sync(0xffffffffu, sm, o); if (lane >= o) sm += v;
        v     = __shfl_up_sync(0xffffffffu, sp, o); if (lane >= o) sp += v;
    }
    if (lane == 31) { wm[wid] = sm; wp[wid] = sp; }
    __syncthreads();
    if (wid == 0) {
        int a = wm[lane], c = wp[lane];
        #pragma unroll
        for (int o = 1; o < 32; o <<= 1) {
            int v = __shfl_up_sync(0xffffffffu, a, o); if (lane >= o) a += v;
            v     = __shfl_up_sync(0xffffffffu, c, o); if (lane >= o) c += v;
        }
        wm[lane] = a; wp[lane] = c;
        if (lane == 31) tot = a;
    }
    __syncthreads();
    int basem = sm - cm + (wid ? wm[wid - 1] : 0);
    int basep = sp - cp + (wid ? wp[wid - 1] : 0);
    int Ktot = tot;

    int km = basem, kp = basep;
    for (int r = 0; r < 16; r++) {
        int j = base_j + r;
        fwd_src[j] = -1;
        if (m_bits & (1u << r)) { Pmask[km] = j; scat_src[j] = km; km++; }
        else scat_src[j] = -1;
        if (p_bits & (1u << r)) { Ppm[kp] = j; kp++; }
    }
    __syncthreads();
    for (int k = tid; k < Ktot; k += 1024) fwd_src[Ppm[k]] = Pmask[k];
    __syncthreads();
    for (int r = 0; r < 16; r++) {
        int j = base_j + r;
        int t = j >> 10, b = j & 1023;
        int sl = seq_len[b];
        bwd_src[j] = (t < sl) ? fwd_src[(sl - 1 - t) * Bb_ + b] : -1;
    }
}

// ---------------- K4: init h (fp32 + tf32-rounded copy) ----------------------
__global__ void __launch_bounds__(256) k_prep_h0(
    const float* __restrict__ src, float* __restrict__ h, float* __restrict__ hr, int n)
{
    int i = blockIdx.x * blockDim.x + threadIdx.x;
    if (i < n) {
        float v = src[i];
        h[i] = v;
        hr[i] = roundtf(v);
    }
}

// ---------------- K4b/c/d: pre-round weights ---------------------------------
__global__ void __launch_bounds__(256) k_prep_wi(
    const float* __restrict__ Wi_f, const float* __restrict__ Wi_b,
    float* __restrict__ wit)
{
    long idx = (long)blockIdx.x * 256 + threadIdx.x;
    if (idx >= (long)NC * H3 * TP) return;
    int k = (int)(idx % TP);
    long r2 = idx / TP;
    int n = (int)(r2 % H3);
    int z = (int)(r2 / H3);
    int i = z >> 1, d = z & 1;
    const float* src = d ? Wi_b : Wi_f;
    wit[idx] = roundtf(src[((long)i * H3 + n) * TP + k]);
}

__global__ void __launch_bounds__(256) k_prep_wh(
    const float* __restrict__ Wh_f, const float* __restrict__ Wh_b,
    float* __restrict__ wht)
{
    long idx = (long)blockIdx.x * 256 + threadIdx.x;
    if (idx >= (long)NC * H3 * Hh) return;
    int k = (int)(idx % Hh);
    long r2 = idx / Hh;
    int n = (int)(r2 % H3);
    int z = (int)(r2 / H3);
    int i = z >> 1, d = z & 1;
    const float* src = d ? Wh_b : Wh_f;
    wht[idx] = roundtf(src[((long)i * H3 + n) * Hh + k]);
}

__global__ void __launch_bounds__(256) k_prep_w1(
    const float* __restrict__ W1, float* __restrict__ w1t)
{
    long idx = (long)blockIdx.x * 256 + threadIdx.x;
    if (idx >= (long)NA * Hh * H2) return;
    w1t[idx] = roundtf(W1[idx]);
}

// ---------------- K5: gather x rows per chain (writes tf32-rounded) ----------
// 256 threads, 4 rows per block
__global__ void __launch_bounds__(256) k_gather(
    const float* __restrict__ plans, const float* __restrict__ comm_plans,
    const float* __restrict__ dummy,
    const int* __restrict__ fwd_src, const int* __restrict__ bwd_src,
    const int* __restrict__ empty, float* __restrict__ xg)
{
    int j = blockIdx.x * 4 + (threadIdx.x >> 6);   // packed row (t*B+b)
    int z = blockIdx.y;                            // chain
    int c = (threadIdx.x & 63) * 4;                // feature quad
    int i = z >> 1, d = z & 1;
    int src = (d ? bwd_src : fwd_src)[j];
    float4 v = make_float4(0.f, 0.f, 0.f, 0.f);
    if (src >= 0) {
        int ts = src >> 10, bs = src & 1023;
        if (ts < NA) {
            if (c < Pp_) {
                v = *reinterpret_cast<const float4*>(&plans[((long)bs * NA + i) * Pp_ + c]);
            } else {
                const float* sp = empty[bs] ? plans : comm_plans;
                v = *reinterpret_cast<const float4*>(&sp[((long)bs * NA + ts) * Pp_ + (c - Pp_)]);
            }
        } else {
            v = *reinterpret_cast<const float4*>(
                &dummy[(((long)i * (NDm - NA) + (ts - NA)) * Bb_ + bs) * TP + c]);
        }
    }
    v.x = roundtf(v.x); v.y = roundtf(v.y); v.z = roundtf(v.z); v.w = roundtf(v.w);
    *reinterpret_cast<float4*>(&xg[((long)z * ROWS + j) * TP + c]) = v;
}

// ---------------- tf32 tensor-core NT GEMM, pre-rounded, 4-stage pipeline ----
#define BM 128
#define BN 128
#define BKq 16
#define SSTR 20
#define GSTG_W ((BM + BN) * SSTR)     // 5120 words per stage
#define GSMEM_BYTES (4 * GSTG_W * 4)  // 81920

__device__ __forceinline__ void cpa16(uint32_t dst, const float* src) {
    asm volatile("cp.async.ca.shared.global [%0], [%1], 16;" :: "r"(dst), "l"(src));
}

__global__ void __launch_bounds__(256, 2) gemm_pre(
    const float* __restrict__ Abase, const float* __restrict__ Wbase,
    float* __restrict__ Cbase, const float* __restrict__ biasBase,
    int M, int N, int K,
    long sA, long sB, long sC, long sBias, int relu)
{
    extern __shared__ float dynsm[];
    int z = blockIdx.z;
    const float* A = Abase + (long)z * sA;
    const float* W = Wbase + (long)z * sB;
    float* C = Cbase + (long)z * sC;
    const float* bias = biasBase ? (biasBase + (long)z * sBias) : nullptr;

    int tid  = threadIdx.x;
    int lane = tid & 31;
    int warp = tid >> 5;
    int wm   = warp & 3;
    int wn   = warp >> 2;
    int m0   = blockIdx.x * BM;
    int n0   = blockIdx.y * BN;

    uint32_t smem_base = (uint32_t)__cvta_generic_to_shared((void*)dynsm);

    float acc[2][8][4];
    #pragma unroll
    for (int a = 0; a < 2; a++)
        #pragma unroll
        for (int b = 0; b < 8; b++)
            #pragma unroll
            for (int c = 0; c < 4; c++) acc[a][b][c] = 0.f;

    int lrow = tid >> 2;
    int lkq  = (tid & 3) * 4;

    auto load_stage = [&](int buf, int k0) {
        uint32_t sAa = smem_base + (buf * GSTG_W) * 4;
        uint32_t sBb = smem_base + (buf * GSTG_W + BM * SSTR) * 4;
        #pragma unroll
        for (int p = 0; p < 2; p++) {
            int row = lrow + p * 64;
            cpa16(sAa + (row * SSTR + lkq) * 4, &A[(long)(m0 + row) * K + k0 + lkq]);
            cpa16(sBb + (row * SSTR + lkq) * 4, &W[(long)(n0 + row) * K + k0 + lkq]);
        }
    };

    const int NSTG = K / BKq;
    // prefetch 3 stages
    load_stage(0, 0);
    asm volatile("cp.async.commit_group;");
    if (NSTG > 1) { load_stage(1, BKq); }
    asm volatile("cp.async.commit_group;");
    if (NSTG > 2) { load_stage(2, 2 * BKq); }
    asm volatile("cp.async.commit_group;");

    for (int s = 0; s < NSTG; s++) {
        int rem = NSTG - 1 - s;               // groups committed after stage s
        if (rem >= 2)      asm volatile("cp.async.wait_group 2;");
        else if (rem == 1) asm volatile("cp.async.wait_group 1;");
        else               asm volatile("cp.async.wait_group 0;");
        __syncthreads();
        if (s + 3 < NSTG) {
            load_stage((s + 3) & 3, (s + 3) * BKq);
            asm volatile("cp.async.commit_group;");
        } else {
            asm volatile("cp.async.commit_group;");   // empty group keeps counts aligned
        }
        const uint32_t* Ash = reinterpret_cast<const uint32_t*>(dynsm + (s & 3) * GSTG_W);
        const uint32_t* Bsh = Ash + BM * SSTR;

        #pragma unroll
        for (int ks = 0; ks < BKq; ks += 8) {
            uint32_t afr[2][4], bfr[8][2];
            int ar = wm * 32 + (lane >> 2);
            int ac = ks + (lane & 3);
            #pragma unroll
            for (int mt = 0; mt < 2; mt++) {
                int r = ar + mt * 16;
                afr[mt][0] = Ash[r * SSTR + ac];
                afr[mt][1] = Ash[(r + 8) * SSTR + ac];
                afr[mt][2] = Ash[r * SSTR + ac + 4];
                afr[mt][3] = Ash[(r + 8) * SSTR + ac + 4];
            }
            int bn = wn * 64 + (lane >> 2);
            int bk = ks + (lane & 3);
            #pragma unroll
            for (int nt = 0; nt < 8; nt++) {
                int n = bn + nt * 8;
                bfr[nt][0] = Bsh[n * SSTR + bk];
                bfr[nt][1] = Bsh[n * SSTR + bk + 4];
            }
            #pragma unroll
            for (int mt = 0; mt < 2; mt++)
                #pragma unroll
                for (int nt = 0; nt < 8; nt++)
                    asm volatile(
                        "mma.sync.aligned.m16n8k8.row.col.f32.tf32.tf32.f32 "
                        "{%0,%1,%2,%3}, {%4,%5,%6,%7}, {%8,%9}, {%0,%1,%2,%3};"
                        : "+f"(acc[mt][nt][0]), "+f"(acc[mt][nt][1]),
                          "+f"(acc[mt][nt][2]), "+f"(acc[mt][nt][3])
                        : "r"(afr[mt][0]), "r"(afr[mt][1]), "r"(afr[mt][2]), "r"(afr[mt][3]),
                          "r"(bfr[nt][0]), "r"(bfr[nt][1]));
        }
    }

    #pragma unroll
    for (int mt = 0; mt < 2; mt++) {
        int r0 = m0 + wm * 32 + mt * 16 + (lane >> 2);
        #pragma unroll
        for (int nt = 0; nt < 8; nt++) {
            int cb = n0 + wn * 64 + nt * 8 + (lane & 3) * 2;
            float v0 = acc[mt][nt][0], v1 = acc[mt][nt][1];
            float v2 = acc[mt][nt][2], v3 = acc[mt][nt][3];
            if (bias) {
                float b0v = bias[cb], b1v = bias[cb + 1];
                v0 += b0v; v1 += b1v; v2 += b0v; v3 += b1v;
            }
            if (relu) {
                v0 = fmaxf(v0, 0.f); v1 = fmaxf(v1, 0.f);
                v2 = fmaxf(v2, 0.f); v3 = fmaxf(v3, 0.f);
            }
            *reinterpret_cast<float2*>(&C[(long)r0 * N + cb])       = make_float2(v0, v1);
            *reinterpret_cast<float2*>(&C[(long)(r0 + 8) * N + cb]) = make_float2(v2, v3);
        }
    }
}

// ---------------- K6: GRU gates, float4 vectorized ----------------------------
__global__ void __launch_bounds__(64) k_gates(
    const float* __restrict__ gi, const float* __restrict__ gh,
    float* __restrict__ h, float* __restrict__ hr,
    float* __restrict__ outf, float* __restrict__ outb,
    const int* __restrict__ seq_len, int t)
{
    int b = blockIdx.x;          // batch
    int z = blockIdx.y;          // chain
    int c4 = threadIdx.x * 4;    // hidden col quad (64 threads x 4 = 256)
    int i = z >> 1, d = z & 1;
    long gio = ((long)z * ROWS + t * Bb_ + b) * H3 + c4;
    long gho = ((long)z * Bb_ + b) * H3 + c4;
    long ho  = ((long)z * Bb_ + b) * Hh + c4;
    float4 gir = *reinterpret_cast<const float4*>(&gi[gio]);
    float4 giz = *reinterpret_cast<const float4*>(&gi[gio + Hh]);
    float4 gin = *reinterpret_cast<const float4*>(&gi[gio + 2 * Hh]);
    float4 ghr = *reinterpret_cast<const float4*>(&gh[gho]);
    float4 ghz = *reinterpret_cast<const float4*>(&gh[gho + Hh]);
    float4 ghn = *reinterpret_cast<const float4*>(&gh[gho + 2 * Hh]);
    float4 hp  = *reinterpret_cast<const float4*>(&h[ho]);
    bool v = t < seq_len[b];

    float4 hn4, o4, hr4;
    {
        float r  = 1.f / (1.f + expf(-(gir.x + ghr.x)));
        float zz = 1.f / (1.f + expf(-(giz.x + ghz.x)));
        float nn = tanhf(gin.x + r * ghn.x);
        float hv = (1.f - zz) * nn + zz * hp.x;
        hn4.x = v ? hv : hp.x;  o4.x = v ? hv : 0.f;
    }
    {
        float r  = 1.f / (1.f + expf(-(gir.y + ghr.y)));
        float zz = 1.f / (1.f + expf(-(giz.y + ghz.y)));
        float nn = tanhf(gin.y + r * ghn.y);
        float hv = (1.f - zz) * nn + zz * hp.y;
        hn4.y = v ? hv : hp.y;  o4.y = v ? hv : 0.f;
    }
    {
        float r  = 1.f / (1.f + expf(-(gir.z + ghr.z)));
        float zz = 1.f / (1.f + expf(-(giz.z + ghz.z)));
        float nn = tanhf(gin.z + r * ghn.z);
        float hv = (1.f - zz) * nn + zz * hp.z;
        hn4.z = v ? hv : hp.z;  o4.z = v ? hv : 0.f;
    }
    {
        float r  = 1.f / (1.f + expf(-(gir.w + ghr.w)));
        float zz = 1.f / (1.f + expf(-(giz.w + ghz.w)));
        float nn = tanhf(gin.w + r * ghn.w);
        float hv = (1.f - zz) * nn + zz * hp.w;
        hn4.w = v ? hv : hp.w;  o4.w = v ? hv : 0.f;
    }
    hr4.x = roundtf(hn4.x); hr4.y = roundtf(hn4.y);
    hr4.z = roundtf(hn4.z); hr4.w = roundtf(hn4.w);

    *reinterpret_cast<float4*>(&h[ho])  = hn4;
    *reinterpret_cast<float4*>(&hr[ho]) = hr4;
    float* op = (d == 0 ? outf : outb) + ((long)i * ROWS + t * Bb_ + b) * Hh + c4;
    *reinterpret_cast<float4*>(op) = o4;
}

// ---------------- K7: scatter + reverse + layernorm (writes rounded) ---------
__global__ void __launch_bounds__(128) k_scores_ln(
    const float* __restrict__ outf, const float* __restrict__ outb,
    const int* __restrict__ scat, const int* __restrict__ seq_len,
    const float* __restrict__ ln_g, const float* __restrict__ ln_b,
    float* __restrict__ scln)
{
    int j = blockIdx.x;          // row (t*B+b) in mask layout
    int i = blockIdx.y;          // agent
    int tid = threadIdx.x;       // 128 threads, 4 cols each
    __shared__ float s1[128], s2[128];
    float v0 = 0.f, v1 = 0.f, v2 = 0.f, v3 = 0.f;
    int k = scat[j];
    if (k >= 0) {
        int tp = k >> 10, bp = k & 1023;
        if (tid < 64) {
            float4 f = *reinterpret_cast<const float4*>(&outf[((long)i * ROWS + k) * Hh + tid * 4]);
            v0 = f.x; v1 = f.y; v2 = f.z; v3 = f.w;
        } else {
            int sl = seq_len[bp];
            if (tp < sl) {
                int rb = sl - 1 - tp;
                float4 f = *reinterpret_cast<const float4*>(
                    &outb[((long)i * ROWS + rb * Bb_ + bp) * Hh + (tid - 64) * 4]);
                v0 = f.x; v1 = f.y; v2 = f.z; v3 = f.w;
            }
        }
    }
    s1[tid] = v0 + v1 + v2 + v3;
    s2[tid] = v0 * v0 + v1 * v1 + v2 * v2 + v3 * v3;
    __syncthreads();
    for (int off = 64; off > 0; off >>= 1) {
        if (tid < off) { s1[tid] += s1[tid + off]; s2[tid] += s2[tid + off]; }
        __syncthreads();
    }
    float mu  = s1[0] * (1.f / H2);
    float var = s2[0] * (1.f / H2) - mu * mu;
    float rs  = rsqrtf(var + 1e-5f);
    int c = tid * 4;
    const float* g = &ln_g[i * H2 + c];
    const float* bt = &ln_b[i * H2 + c];
    float4 o;
    o.x = roundtf((v0 - mu) * rs * g[0] + bt[0]);
    o.y = roundtf((v1 - mu) * rs * g[1] + bt[1]);
    o.z = roundtf((v2 - mu) * rs * g[2] + bt[2]);
    o.w = roundtf((v3 - mu) * rs * g[3] + bt[3]);
    *reinterpret_cast<float4*>(&scln[((long)i * ROWS + j) * H2 + c]) = o;
}

// ---------------- K8: final 2-wide projection --------------------------------
__global__ void __launch_bounds__(256) k_w2out(
    const float* __restrict__ h1, const float* __restrict__ W2,
    const float* __restrict__ b2, float* __restrict__ out)
{
    int gw = (blockIdx.x * blockDim.x + threadIdx.x) >> 5;
    int lane = threadIdx.x & 31;
    if (gw >= NA * ROWS) return;
    int i = gw >> 14;
    int j = gw & 16383;
    const float* hr = &h1[((long)i * ROWS + j) * Hh];
    const float* w0 = &W2[(i * 2 + 0) * Hh];
    const float* w1 = &W2[(i * 2 + 1) * Hh];
    float a0 = 0.f, a1 = 0.f;
    #pragma unroll
    for (int q = 0; q < 8; q++) {
        float hv = hr[lane + q * 32];
        a0 = fmaf(hv, w0[lane + q * 32], a0);
        a1 = fmaf(hv, w1[lane + q * 32], a1);
    }
    #pragma unroll
    for (int o = 16; o > 0; o >>= 1) {
        a0 += __shfl_down_sync(0xffffffffu, a0, o);
        a1 += __shfl_down_sync(0xffffffffu, a1, o);
    }
    if (lane == 0) {
        int t = j >> 10, b = j & 1023;
        long base = (((long)i * NDm + t) * Bb_ + b) * 2;
        out[base + 0] = a0 + b2[i * 2 + 0];
        out[base + 1] = a1 + b2[i * 2 + 1];
    }
}

// ---------------- K9: copy final hidden states to output ---------------------
__global__ void __launch_bounds__(256) k_copy_hx(
    const float* __restrict__ h, float* __restrict__ out, int n)
{
    int i = blockIdx.x * blockDim.x + threadIdx.x;
    if (i < n) out[i] = h[i];
}

// ---------------- host orchestration -----------------------------------------
extern "C" void kernel_launch(void* const* d_in, const int* in_sizes, int n_in,
                              void* d_out, int out_size)
{
    const float* plans         = (const float*)d_in[0];
    const float* comm_plans    = (const float*)d_in[1];
    const float* coord_hiddens = (const float*)d_in[2];
    const float* dummy_noise   = (const float*)d_in[3];
    const float* Wi_f = (const float*)d_in[4];
    const float* Wh_f = (const float*)d_in[5];
    const float* Wi_b = (const float*)d_in[6];
    const float* Wh_b = (const float*)d_in[7];
    const float* ln_g = (const float*)d_in[8];
    const float* ln_b = (const float*)d_in[9];
    const float* W1   = (const float*)d_in[10];
    const float* b1   = (const float*)d_in[11];
    const float* W2   = (const float*)d_in[12];
    const float* b2   = (const float*)d_in[13];
    float* out = (float*)d_out;

    float *xg, *gi, *gh, *outf, *outb, *scln, *h1, *hst, *hr, *wit, *wht, *w1t;
    int *fwd, *bwd, *scat, *Pm, *Pp, *seq, *emp, *anyc, *anyp;
    unsigned char* mreal;
    cudaGetSymbolAddress((void**)&xg,   g_xg);
    cudaGetSymbolAddress((void**)&gi,   g_gi);
    cudaGetSymbolAddress((void**)&gh,   g_gh);
    cudaGetSymbolAddress((void**)&outf, g_outf);
    cudaGetSymbolAddress((void**)&outb, g_outb);
    cudaGetSymbolAddress((void**)&scln, g_scln);
    cudaGetSymbolAddress((void**)&h1,   g_h1);
    cudaGetSymbolAddress((void**)&hst,  g_h);
    cudaGetSymbolAddress((void**)&hr,   g_hr);
    cudaGetSymbolAddress((void**)&wit,  g_wit);
    cudaGetSymbolAddress((void**)&wht,  g_wht);
    cudaGetSymbolAddress((void**)&w1t,  g_w1t);
    cudaGetSymbolAddress((void**)&fwd,  g_fwd);
    cudaGetSymbolAddress((void**)&bwd,  g_bwd);
    cudaGetSymbolAddress((void**)&scat, g_scat);
    cudaGetSymbolAddress((void**)&Pm,   g_Pmask);
    cudaGetSymbolAddress((void**)&Pp,   g_Ppm);
    cudaGetSymbolAddress((void**)&seq,  g_seq);
    cudaGetSymbolAddress((void**)&emp,  g_empty);
    cudaGetSymbolAddress((void**)&anyc, g_anyc);
    cudaGetSymbolAddress((void**)&anyp, g_anyp);
    cudaGetSymbolAddress((void**)&mreal, g_mreal);

    cudaFuncSetAttribute(gemm_pre, cudaFuncAttributeMaxDynamicSharedMemorySize,
                         GSMEM_BYTES);

    // masks + packing indices
    k_rowflags<<<1024, 256>>>(comm_plans, plans, anyc, anyp);
    k_maskreal<<<4, 256>>>(anyc, anyp, emp, mreal);
    k_indices<<<1, 1024>>>(mreal, seq, fwd, bwd, scat, Pm, Pp);

    // init hidden + pre-round weights
    k_prep_h0<<<(NC * Bb_ * Hh + 255) / 256, 256>>>(coord_hiddens, hst, hr, NC * Bb_ * Hh);
    k_prep_wi<<<(int)(((long)NC * H3 * TP + 255) / 256), 256>>>(Wi_f, Wi_b, wit);
    k_prep_wh<<<(int)(((long)NC * H3 * Hh + 255) / 256), 256>>>(Wh_f, Wh_b, wht);
    k_prep_w1<<<(int)(((long)NA * Hh * H2 + 255) / 256), 256>>>(W1, w1t);

    // gather inputs (rounded) and input projections
    k_gather<<<dim3(ROWS / 4, NC), 256>>>(plans, comm_plans, dummy_noise, fwd, bwd, emp, xg);
    gemm_pre<<<dim3(ROWS / BM, H3 / BN, NC), 256, GSMEM_BYTES>>>(
        xg, wit, gi, nullptr,
        ROWS, H3, TP,
        (long)ROWS * TP, (long)H3 * TP, (long)ROWS * H3, 0, 0);

    // 16 recurrent steps: gh GEMM + gates
    for (int t = 0; t < NDm; t++) {
        gemm_pre<<<dim3(Bb_ / BM, H3 / BN, NC), 256, GSMEM_BYTES>>>(
            hr, wht, gh, nullptr,
            Bb_, H3, Hh,
            (long)Bb_ * Hh, (long)H3 * Hh, (long)Bb_ * H3, 0, 0);
        k_gates<<<dim3(Bb_, NC), 64>>>(gi, gh, hst, hr, outf, outb, seq, t);
    }

    // scatter + reverse + layernorm (rounded output)
    k_scores_ln<<<dim3(ROWS, NA), 128>>>(outf, outb, scat, seq, ln_g, ln_b, scln);

    // MLP: h1 = relu(scln @ W1^T + b1)
    gemm_pre<<<dim3(ROWS / BM, Hh / BN, NA), 256, GSMEM_BYTES>>>(
        scln, w1t, h1, b1,
        ROWS, Hh, H2,
        (long)ROWS * H2, (long)Hh * H2, (long)ROWS * Hh, Hh, 1);

    // final projection -> coord_masks (N, ND, B, 2)
    k_w2out<<<(NA * ROWS * 32 + 255) / 256, 256>>>(h1, W2, b2, out);

    // coord_rnn_hxs (N, 2, B, H) appended after coord_masks
    int masks_elems = NA * NDm * Bb_ * 2;
    int hx_elems = NC * Bb_ * Hh;
    if (out_size >= masks_elems + hx_elems) {
        k_copy_hx<<<(hx_elems + 255) / 256, 256>>>(hst, out + masks_elems, hx_elems);
    }
}

// round 17
// speedup vs baseline: 1.3310x; 1.0132x over previous
#include <cuda_runtime.h>
#include <math.h>
#include <stdint.h>

// Problem constants
#define NA   8      // agents
#define NDm  16     // N_DUMMY (timesteps)
#define Bb_  1024   // batch
#define Pp_  128    // plan
#define TP   256    // 2*P
#define Hh   256    // hidden
#define H3   768    // 3*H
#define H2   512    // 2*H
#define NC   16     // chains = agents * 2 dirs
#define ROWS 16384  // NDm * Bb_

// ---------------- scratch (device globals; no allocation allowed) -------------
__device__ float g_xg[NC * ROWS * TP];        // gathered inputs (tf32-rounded)
__device__ float g_gi[(long)NC * ROWS * H3];  // input projections
__device__ float g_gh[NC * Bb_ * H3];         // per-step hidden projections
__device__ float g_outf[NA * ROWS * Hh];      // forward GRU outputs
__device__ float g_outb[NA * ROWS * Hh];      // backward GRU outputs
__device__ float g_scln[NA * ROWS * H2];      // scattered + LN (tf32-rounded)
__device__ float g_part[NA * ROWS * 2 * 2];   // W2 partials [i][row][ytile][o]
__device__ float g_h[NC * Bb_ * Hh];          // GRU hidden state (fp32)
__device__ float g_hr[NC * Bb_ * Hh];         // tf32-rounded shadow of h
__device__ float g_wit[(long)NC * H3 * TP];   // pre-rounded Wi per chain
__device__ float g_wht[NC * H3 * Hh];         // pre-rounded Wh per chain
__device__ float g_w1t[NA * Hh * H2];         // pre-rounded W1
__device__ int   g_fwd[ROWS], g_bwd[ROWS], g_scat[ROWS];
__device__ int   g_Pmask[ROWS], g_Ppm[ROWS];
__device__ int   g_seq[Bb_], g_empty[Bb_];
__device__ int   g_anyc[Bb_ * NA], g_anyp[Bb_ * NA];
__device__ unsigned char g_mreal[NA * Bb_];

__device__ __forceinline__ uint32_t f2tf32(float f) {
    uint32_t u;
    asm("cvt.rna.tf32.f32 %0, %1;" : "=r"(u) : "f"(f));
    return u;
}
__device__ __forceinline__ float roundtf(float f) {
    return __uint_as_float(f2tf32(f));
}

// ---------------- K1: per-(b,n) nonzero row flags ----------------------------
__global__ void __launch_bounds__(256) k_rowflags(
    const float* __restrict__ comm_plans,
    const float* __restrict__ plans,
    int* __restrict__ anyc, int* __restrict__ anyp)
{
    int warp = (blockIdx.x * blockDim.x + threadIdx.x) >> 5;
    int lane = threadIdx.x & 31;
    if (warp >= Bb_ * NA) return;
    float4 c4 = *reinterpret_cast<const float4*>(&comm_plans[(long)warp * Pp_ + lane * 4]);
    bool nzc = (c4.x != 0.f) || (c4.y != 0.f) || (c4.z != 0.f) || (c4.w != 0.f);
    unsigned mc = __ballot_sync(0xffffffffu, nzc);
    float4 p4 = *reinterpret_cast<const float4*>(&plans[(long)warp * Pp_ + lane * 4]);
    bool nzp = (p4.x != 0.f) || (p4.y != 0.f) || (p4.z != 0.f) || (p4.w != 0.f);
    unsigned mp = __ballot_sync(0xffffffffu, nzp);
    if (lane == 0) { anyc[warp] = (mc != 0u); anyp[warp] = (mp != 0u); }
}

// ---------------- K2: empty[b], mask_real[n][b] ------------------------------
__global__ void __launch_bounds__(256) k_maskreal(
    const int* __restrict__ anyc, const int* __restrict__ anyp,
    int* __restrict__ empty, unsigned char* __restrict__ mreal)
{
    int b = blockIdx.x * blockDim.x + threadIdx.x;
    if (b >= Bb_) return;
    int any = 0, ac[NA];
    #pragma unroll
    for (int n = 0; n < NA; n++) { ac[n] = anyc[b * NA + n]; any |= ac[n]; }
    int e = !any;
    empty[b] = e;
    #pragma unroll
    for (int n = 0; n < NA; n++)
        mreal[n * Bb_ + b] = e ? (unsigned char)anyp[b * NA + n] : (unsigned char)ac[n];
}

// ---------------- K3: packing index maps (single block) ----------------------
__global__ void __launch_bounds__(1024) k_indices(
    const unsigned char* __restrict__ mreal,
    int* __restrict__ seq_len,
    int* __restrict__ fwd_src, int* __restrict__ bwd_src,
    int* __restrict__ scat_src,
    int* __restrict__ Pmask, int* __restrict__ Ppm)
{
    int tid = threadIdx.x;            // 1024 threads
    {
        int b = tid, s = NDm - NA;
        #pragma unroll
        for (int t = 0; t < NA; t++) s += mreal[t * Bb_ + b];
        seq_len[b] = s;
    }
    __syncthreads();

    int base_j = tid * 16;
    unsigned m_bits = 0, p_bits = 0;
    int cm = 0, cp = 0;
    for (int r = 0; r < 16; r++) {
        int j = base_j + r;
        int t = j >> 10, b = j & 1023;
        int m = (t < NA) ? (int)mreal[j] : 1;
        int p = (t < seq_len[b]) ? 1 : 0;
        if (m) { m_bits |= 1u << r; cm++; }
        if (p) { p_bits |= 1u << r; cp++; }
    }
    __shared__ int wm[32], wp[32], tot;
    int lane = tid & 31, wid = tid >> 5;
    int sm = cm, sp = cp;
    #pragma unroll
    for (int o = 1; o < 32; o <<= 1) {
        int v = __shfl_up_sync(0xffffffffu, sm, o); if (lane >= o) sm += v;
        v     = __shfl_up_sync(0xffffffffu, sp, o); if (lane >= o) sp += v;
    }
    if (lane == 31) { wm[wid] = sm; wp[wid] = sp; }
    __syncthreads();
    if (wid == 0) {
        int a = wm[lane], c = wp[lane];
        #pragma unroll
        for (int o = 1; o < 32; o <<= 1) {
            int v = __shfl_up_sync(0xffffffffu, a, o); if (lane >= o) a += v;
            v     = __shfl_up_sync(0xffffffffu, c, o); if (lane >= o) c += v;
        }
        wm[lane] = a; wp[lane] = c;
        if (lane == 31) tot = a;
    }
    __syncthreads();
    int basem = sm - cm + (wid ? wm[wid - 1] : 0);
    int basep = sp - cp + (wid ? wp[wid - 1] : 0);
    int Ktot = tot;

    int km = basem, kp = basep;
    for (int r = 0; r < 16; r++) {
        int j = base_j + r;
        fwd_src[j] = -1;
        if (m_bits & (1u << r)) { Pmask[km] = j; scat_src[j] = km; km++; }
        else scat_src[j] = -1;
        if (p_bits & (1u << r)) { Ppm[kp] = j; kp++; }
    }
    __syncthreads();
    for (int k = tid; k < Ktot; k += 1024) fwd_src[Ppm[k]] = Pmask[k];
    __syncthreads();
    for (int r = 0; r < 16; r++) {
        int j = base_j + r;
        int t = j >> 10, b = j & 1023;
        int sl = seq_len[b];
        bwd_src[j] = (t < sl) ? fwd_src[(sl - 1 - t) * Bb_ + b] : -1;
    }
}

// ---------------- K4: init h (fp32 + tf32-rounded copy) ----------------------
__global__ void __launch_bounds__(256) k_prep_h0(
    const float* __restrict__ src, float* __restrict__ h, float* __restrict__ hr, int n)
{
    int i = blockIdx.x * blockDim.x + threadIdx.x;
    if (i < n) {
        float v = src[i];
        h[i] = v;
        hr[i] = roundtf(v);
    }
}

// ---------------- K4b/c/d: pre-round weights ---------------------------------
__global__ void __launch_bounds__(256) k_prep_wi(
    const float* __restrict__ Wi_f, const float* __restrict__ Wi_b,
    float* __restrict__ wit)
{
    long idx = (long)blockIdx.x * 256 + threadIdx.x;
    if (idx >= (long)NC * H3 * TP) return;
    int k = (int)(idx % TP);
    long r2 = idx / TP;
    int n = (int)(r2 % H3);
    int z = (int)(r2 / H3);
    int i = z >> 1, d = z & 1;
    const float* src = d ? Wi_b : Wi_f;
    wit[idx] = roundtf(src[((long)i * H3 + n) * TP + k]);
}

__global__ void __launch_bounds__(256) k_prep_wh(
    const float* __restrict__ Wh_f, const float* __restrict__ Wh_b,
    float* __restrict__ wht)
{
    long idx = (long)blockIdx.x * 256 + threadIdx.x;
    if (idx >= (long)NC * H3 * Hh) return;
    int k = (int)(idx % Hh);
    long r2 = idx / Hh;
    int n = (int)(r2 % H3);
    int z = (int)(r2 / H3);
    int i = z >> 1, d = z & 1;
    const float* src = d ? Wh_b : Wh_f;
    wht[idx] = roundtf(src[((long)i * H3 + n) * Hh + k]);
}

__global__ void __launch_bounds__(256) k_prep_w1(
    const float* __restrict__ W1, float* __restrict__ w1t)
{
    long idx = (long)blockIdx.x * 256 + threadIdx.x;
    if (idx >= (long)NA * Hh * H2) return;
    w1t[idx] = roundtf(W1[idx]);
}

// ---------------- K5: gather x rows per chain (writes tf32-rounded) ----------
__global__ void __launch_bounds__(256) k_gather(
    const float* __restrict__ plans, const float* __restrict__ comm_plans,
    const float* __restrict__ dummy,
    const int* __restrict__ fwd_src, const int* __restrict__ bwd_src,
    const int* __restrict__ empty, float* __restrict__ xg)
{
    int j = blockIdx.x * 4 + (threadIdx.x >> 6);   // packed row (t*B+b)
    int z = blockIdx.y;                            // chain
    int c = (threadIdx.x & 63) * 4;                // feature quad
    int i = z >> 1, d = z & 1;
    int src = (d ? bwd_src : fwd_src)[j];
    float4 v = make_float4(0.f, 0.f, 0.f, 0.f);
    if (src >= 0) {
        int ts = src >> 10, bs = src & 1023;
        if (ts < NA) {
            if (c < Pp_) {
                v = *reinterpret_cast<const float4*>(&plans[((long)bs * NA + i) * Pp_ + c]);
            } else {
                const float* sp = empty[bs] ? plans : comm_plans;
                v = *reinterpret_cast<const float4*>(&sp[((long)bs * NA + ts) * Pp_ + (c - Pp_)]);
            }
        } else {
            v = *reinterpret_cast<const float4*>(
                &dummy[(((long)i * (NDm - NA) + (ts - NA)) * Bb_ + bs) * TP + c]);
        }
    }
    v.x = roundtf(v.x); v.y = roundtf(v.y); v.z = roundtf(v.z); v.w = roundtf(v.w);
    *reinterpret_cast<float4*>(&xg[((long)z * ROWS + j) * TP + c]) = v;
}

// ---------------- tf32 tensor-core NT GEMM, pre-rounded, 4-stage pipeline ----
#define BM 128
#define BN 128
#define BKq 16
#define SSTR 20
#define GSTG_W ((BM + BN) * SSTR)     // 5120 words per stage
#define GSMEM_BYTES (4 * GSTG_W * 4)  // 81920

__device__ __forceinline__ void cpa16(uint32_t dst, const float* src) {
    asm volatile("cp.async.ca.shared.global [%0], [%1], 16;" :: "r"(dst), "l"(src));
}

__global__ void __launch_bounds__(256, 2) gemm_pre(
    const float* __restrict__ Abase, const float* __restrict__ Wbase,
    float* __restrict__ Cbase, const float* __restrict__ biasBase,
    int M, int N, int K,
    long sA, long sB, long sC, long sBias, int relu)
{
    extern __shared__ float dynsm[];
    int z = blockIdx.z;
    const float* A = Abase + (long)z * sA;
    const float* W = Wbase + (long)z * sB;
    float* C = Cbase + (long)z * sC;
    const float* bias = biasBase ? (biasBase + (long)z * sBias) : nullptr;

    int tid  = threadIdx.x;
    int lane = tid & 31;
    int warp = tid >> 5;
    int wm   = warp & 3;
    int wn   = warp >> 2;
    int m0   = blockIdx.x * BM;
    int n0   = blockIdx.y * BN;

    uint32_t smem_base = (uint32_t)__cvta_generic_to_shared((void*)dynsm);

    float acc[2][8][4];
    #pragma unroll
    for (int a = 0; a < 2; a++)
        #pragma unroll
        for (int b = 0; b < 8; b++)
            #pragma unroll
            for (int c = 0; c < 4; c++) acc[a][b][c] = 0.f;

    int lrow = tid >> 2;
    int lkq  = (tid & 3) * 4;

    auto load_stage = [&](int buf, int k0) {
        uint32_t sAa = smem_base + (buf * GSTG_W) * 4;
        uint32_t sBb = smem_base + (buf * GSTG_W + BM * SSTR) * 4;
        #pragma unroll
        for (int p = 0; p < 2; p++) {
            int row = lrow + p * 64;
            cpa16(sAa + (row * SSTR + lkq) * 4, &A[(long)(m0 + row) * K + k0 + lkq]);
            cpa16(sBb + (row * SSTR + lkq) * 4, &W[(long)(n0 + row) * K + k0 + lkq]);
        }
    };

    const int NSTG = K / BKq;
    load_stage(0, 0);
    asm volatile("cp.async.commit_group;");
    if (NSTG > 1) { load_stage(1, BKq); }
    asm volatile("cp.async.commit_group;");
    if (NSTG > 2) { load_stage(2, 2 * BKq); }
    asm volatile("cp.async.commit_group;");

    for (int s = 0; s < NSTG; s++) {
        int rem = NSTG - 1 - s;
        if (rem >= 2)      asm volatile("cp.async.wait_group 2;");
        else if (rem == 1) asm volatile("cp.async.wait_group 1;");
        else               asm volatile("cp.async.wait_group 0;");
        __syncthreads();
        if (s + 3 < NSTG) {
            load_stage((s + 3) & 3, (s + 3) * BKq);
            asm volatile("cp.async.commit_group;");
        } else {
            asm volatile("cp.async.commit_group;");
        }
        const uint32_t* Ash = reinterpret_cast<const uint32_t*>(dynsm + (s & 3) * GSTG_W);
        const uint32_t* Bsh = Ash + BM * SSTR;

        #pragma unroll
        for (int ks = 0; ks < BKq; ks += 8) {
            uint32_t afr[2][4], bfr[8][2];
            int ar = wm * 32 + (lane >> 2);
            int ac = ks + (lane & 3);
            #pragma unroll
            for (int mt = 0; mt < 2; mt++) {
                int r = ar + mt * 16;
                afr[mt][0] = Ash[r * SSTR + ac];
                afr[mt][1] = Ash[(r + 8) * SSTR + ac];
                afr[mt][2] = Ash[r * SSTR + ac + 4];
                afr[mt][3] = Ash[(r + 8) * SSTR + ac + 4];
            }
            int bn = wn * 64 + (lane >> 2);
            int bk = ks + (lane & 3);
            #pragma unroll
            for (int nt = 0; nt < 8; nt++) {
                int n = bn + nt * 8;
                bfr[nt][0] = Bsh[n * SSTR + bk];
                bfr[nt][1] = Bsh[n * SSTR + bk + 4];
            }
            #pragma unroll
            for (int mt = 0; mt < 2; mt++)
                #pragma unroll
                for (int nt = 0; nt < 8; nt++)
                    asm volatile(
                        "mma.sync.aligned.m16n8k8.row.col.f32.tf32.tf32.f32 "
                        "{%0,%1,%2,%3}, {%4,%5,%6,%7}, {%8,%9}, {%0,%1,%2,%3};"
                        : "+f"(acc[mt][nt][0]), "+f"(acc[mt][nt][1]),
                          "+f"(acc[mt][nt][2]), "+f"(acc[mt][nt][3])
                        : "r"(afr[mt][0]), "r"(afr[mt][1]), "r"(afr[mt][2]), "r"(afr[mt][3]),
                          "r"(bfr[nt][0]), "r"(bfr[nt][1]));
        }
    }

    #pragma unroll
    for (int mt = 0; mt < 2; mt++) {
        int r0 = m0 + wm * 32 + mt * 16 + (lane >> 2);
        #pragma unroll
        for (int nt = 0; nt < 8; nt++) {
            int cb = n0 + wn * 64 + nt * 8 + (lane & 3) * 2;
            float v0 = acc[mt][nt][0], v1 = acc[mt][nt][1];
            float v2 = acc[mt][nt][2], v3 = acc[mt][nt][3];
            if (bias) {
                float b0v = bias[cb], b1v = bias[cb + 1];
                v0 += b0v; v1 += b1v; v2 += b0v; v3 += b1v;
            }
            if (relu) {
                v0 = fmaxf(v0, 0.f); v1 = fmaxf(v1, 0.f);
                v2 = fmaxf(v2, 0.f); v3 = fmaxf(v3, 0.f);
            }
            *reinterpret_cast<float2*>(&C[(long)r0 * N + cb])       = make_float2(v0, v1);
            *reinterpret_cast<float2*>(&C[(long)(r0 + 8) * N + cb]) = make_float2(v2, v3);
        }
    }
}

// ---------------- MLP GEMM with fused W2 dot-product epilogue ----------------
// h1 tile = relu(scln@W1^T + b1) computed in acc (never stored). Epilogue
// computes per-row partial dots with W2 over this CTA's 128 h1-cols and
// writes partial[i][row][ytile][2].
__global__ void __launch_bounds__(256, 2) gemm_mlp(
    const float* __restrict__ Abase,   // scln
    const float* __restrict__ Wbase,   // w1t
    const float* __restrict__ b1,      // [NA][Hh]
    const float* __restrict__ W2,      // [NA][2][Hh]
    float* __restrict__ part)          // [NA][ROWS][2][2]
{
    extern __shared__ float dynsm[];
    int z = blockIdx.z;
    const int M = ROWS, N = Hh, K = H2;
    const float* A = Abase + (long)z * ROWS * H2;
    const float* W = Wbase + (long)z * Hh * H2;
    const float* bias = b1 + (long)z * Hh;
    const float* w2g = W2 + (long)z * 2 * Hh;

    int tid  = threadIdx.x;
    int lane = tid & 31;
    int warp = tid >> 5;
    int wm   = warp & 3;
    int wn   = warp >> 2;
    int m0   = blockIdx.x * BM;
    int n0   = blockIdx.y * BN;

    uint32_t smem_base = (uint32_t)__cvta_generic_to_shared((void*)dynsm);

    float acc[2][8][4];
    #pragma unroll
    for (int a = 0; a < 2; a++)
        #pragma unroll
        for (int b = 0; b < 8; b++)
            #pragma unroll
            for (int c = 0; c < 4; c++) acc[a][b][c] = 0.f;

    int lrow = tid >> 2;
    int lkq  = (tid & 3) * 4;

    auto load_stage = [&](int buf, int k0) {
        uint32_t sAa = smem_base + (buf * GSTG_W) * 4;
        uint32_t sBb = smem_base + (buf * GSTG_W + BM * SSTR) * 4;
        #pragma unroll
        for (int p = 0; p < 2; p++) {
            int row = lrow + p * 64;
            cpa16(sAa + (row * SSTR + lkq) * 4, &A[(long)(m0 + row) * K + k0 + lkq]);
            cpa16(sBb + (row * SSTR + lkq) * 4, &W[(long)(n0 + row) * K + k0 + lkq]);
        }
    };

    const int NSTG = K / BKq;   // 32
    load_stage(0, 0);
    asm volatile("cp.async.commit_group;");
    load_stage(1, BKq);
    asm volatile("cp.async.commit_group;");
    load_stage(2, 2 * BKq);
    asm volatile("cp.async.commit_group;");

    for (int s = 0; s < NSTG; s++) {
        int rem = NSTG - 1 - s;
        if (rem >= 2)      asm volatile("cp.async.wait_group 2;");
        else if (rem == 1) asm volatile("cp.async.wait_group 1;");
        else               asm volatile("cp.async.wait_group 0;");
        __syncthreads();
        if (s + 3 < NSTG) {
            load_stage((s + 3) & 3, (s + 3) * BKq);
            asm volatile("cp.async.commit_group;");
        } else {
            asm volatile("cp.async.commit_group;");
        }
        const uint32_t* Ash = reinterpret_cast<const uint32_t*>(dynsm + (s & 3) * GSTG_W);
        const uint32_t* Bsh = Ash + BM * SSTR;

        #pragma unroll
        for (int ks = 0; ks < BKq; ks += 8) {
            uint32_t afr[2][4], bfr[8][2];
            int ar = wm * 32 + (lane >> 2);
            int ac = ks + (lane & 3);
            #pragma unroll
            for (int mt = 0; mt < 2; mt++) {
                int r = ar + mt * 16;
                afr[mt][0] = Ash[r * SSTR + ac];
                afr[mt][1] = Ash[(r + 8) * SSTR + ac];
                afr[mt][2] = Ash[r * SSTR + ac + 4];
                afr[mt][3] = Ash[(r + 8) * SSTR + ac + 4];
            }
            int bn = wn * 64 + (lane >> 2);
            int bk = ks + (lane & 3);
            #pragma unroll
            for (int nt = 0; nt < 8; nt++) {
                int n = bn + nt * 8;
                bfr[nt][0] = Bsh[n * SSTR + bk];
                bfr[nt][1] = Bsh[n * SSTR + bk + 4];
            }
            #pragma unroll
            for (int mt = 0; mt < 2; mt++)
                #pragma unroll
                for (int nt = 0; nt < 8; nt++)
                    asm volatile(
                        "mma.sync.aligned.m16n8k8.row.col.f32.tf32.tf32.f32 "
                        "{%0,%1,%2,%3}, {%4,%5,%6,%7}, {%8,%9}, {%0,%1,%2,%3};"
                        : "+f"(acc[mt][nt][0]), "+f"(acc[mt][nt][1]),
                          "+f"(acc[mt][nt][2]), "+f"(acc[mt][nt][3])
                        : "r"(afr[mt][0]), "r"(afr[mt][1]), "r"(afr[mt][2]), "r"(afr[mt][3]),
                          "r"(bfr[nt][0]), "r"(bfr[nt][1]));
        }
    }

    // ---- fused W2 epilogue ----
    float s[2][2][2];   // [mt][rr][o]
    #pragma unroll
    for (int mt = 0; mt < 2; mt++)
        #pragma unroll
        for (int rr = 0; rr < 2; rr++) { s[mt][rr][0] = 0.f; s[mt][rr][1] = 0.f; }

    #pragma unroll
    for (int nt = 0; nt < 8; nt++) {
        #pragma unroll
        for (int cc = 0; cc < 2; cc++) {
            int col = n0 + wn * 64 + nt * 8 + (lane & 3) * 2 + cc;
            float b1v = __ldg(&bias[col]);
            float w20 = __ldg(&w2g[col]);
            float w21 = __ldg(&w2g[Hh + col]);
            #pragma unroll
            for (int mt = 0; mt < 2; mt++)
                #pragma unroll
                for (int rr = 0; rr < 2; rr++) {
                    float v = acc[mt][nt][rr * 2 + cc] + b1v;
                    v = fmaxf(v, 0.f);
                    s[mt][rr][0] = fmaf(v, w20, s[mt][rr][0]);
                    s[mt][rr][1] = fmaf(v, w21, s[mt][rr][1]);
                }
        }
    }
    // quad reduce (lanes sharing lane>>2)
    #pragma unroll
    for (int mt = 0; mt < 2; mt++)
        #pragma unroll
        for (int rr = 0; rr < 2; rr++)
            #pragma unroll
            for (int o = 0; o < 2; o++) {
                float v = s[mt][rr][o];
                v += __shfl_down_sync(0xffffffffu, v, 1, 4);
                v += __shfl_down_sync(0xffffffffu, v, 2, 4);
                s[mt][rr][o] = v;
            }

    __syncthreads();            // pipeline smem no longer needed
    float* red = dynsm;         // [128 rows][2 wn][2 o]
    if ((lane & 3) == 0) {
        #pragma unroll
        for (int mt = 0; mt < 2; mt++)
            #pragma unroll
            for (int rr = 0; rr < 2; rr++) {
                int row = wm * 32 + mt * 16 + rr * 8 + (lane >> 2);
                red[(row * 2 + wn) * 2 + 0] = s[mt][rr][0];
                red[(row * 2 + wn) * 2 + 1] = s[mt][rr][1];
            }
    }
    __syncthreads();
    {
        int row = tid >> 1, o = tid & 1;   // 256 threads -> 128 rows x 2 outs
        float v = red[(row * 2 + 0) * 2 + o] + red[(row * 2 + 1) * 2 + o];
        part[(((long)z * ROWS + m0 + row) * 2 + blockIdx.y) * 2 + o] = v;
    }
}

// ---------------- combine W2 partials + b2 -> coord_masks --------------------
__global__ void __launch_bounds__(256) k_w2combine(
    const float* __restrict__ part, const float* __restrict__ b2,
    float* __restrict__ out)
{
    int idx = blockIdx.x * blockDim.x + threadIdx.x;
    if (idx >= NA * ROWS * 2) return;
    int o = idx & 1;
    int j = (idx >> 1) & (ROWS - 1);
    int i = idx >> 15;
    float v = part[(((long)i * ROWS + j) * 2 + 0) * 2 + o]
            + part[(((long)i * ROWS + j) * 2 + 1) * 2 + o]
            + b2[i * 2 + o];
    int t = j >> 10, b = j & 1023;
    out[(((long)i * NDm + t) * Bb_ + b) * 2 + o] = v;
}

// ---------------- K6: GRU gates, float4 vectorized ----------------------------
__global__ void __launch_bounds__(64) k_gates(
    const float* __restrict__ gi, const float* __restrict__ gh,
    float* __restrict__ h, float* __restrict__ hr,
    float* __restrict__ outf, float* __restrict__ outb,
    const int* __restrict__ seq_len, int t)
{
    int b = blockIdx.x;          // batch
    int z = blockIdx.y;          // chain
    int c4 = threadIdx.x * 4;    // hidden col quad
    int i = z >> 1, d = z & 1;
    long gio = ((long)z * ROWS + t * Bb_ + b) * H3 + c4;
    long gho = ((long)z * Bb_ + b) * H3 + c4;
    long ho  = ((long)z * Bb_ + b) * Hh + c4;
    float4 gir = *reinterpret_cast<const float4*>(&gi[gio]);
    float4 giz = *reinterpret_cast<const float4*>(&gi[gio + Hh]);
    float4 gin = *reinterpret_cast<const float4*>(&gi[gio + 2 * Hh]);
    float4 ghr = *reinterpret_cast<const float4*>(&gh[gho]);
    float4 ghz = *reinterpret_cast<const float4*>(&gh[gho + Hh]);
    float4 ghn = *reinterpret_cast<const float4*>(&gh[gho + 2 * Hh]);
    float4 hp  = *reinterpret_cast<const float4*>(&h[ho]);
    bool v = t < seq_len[b];

    float4 hn4, o4, hr4;
    {
        float r  = 1.f / (1.f + expf(-(gir.x + ghr.x)));
        float zz = 1.f / (1.f + expf(-(giz.x + ghz.x)));
        float nn = tanhf(gin.x + r * ghn.x);
        float hv = (1.f - zz) * nn + zz * hp.x;
        hn4.x = v ? hv : hp.x;  o4.x = v ? hv : 0.f;
    }
    {
        float r  = 1.f / (1.f + expf(-(gir.y + ghr.y)));
        float zz = 1.f / (1.f + expf(-(giz.y + ghz.y)));
        float nn = tanhf(gin.y + r * ghn.y);
        float hv = (1.f - zz) * nn + zz * hp.y;
        hn4.y = v ? hv : hp.y;  o4.y = v ? hv : 0.f;
    }
    {
        float r  = 1.f / (1.f + expf(-(gir.z + ghr.z)));
        float zz = 1.f / (1.f + expf(-(giz.z + ghz.z)));
        float nn = tanhf(gin.z + r * ghn.z);
        float hv = (1.f - zz) * nn + zz * hp.z;
        hn4.z = v ? hv : hp.z;  o4.z = v ? hv : 0.f;
    }
    {
        float r  = 1.f / (1.f + expf(-(gir.w + ghr.w)));
        float zz = 1.f / (1.f + expf(-(giz.w + ghz.w)));
        float nn = tanhf(gin.w + r * ghn.w);
        float hv = (1.f - zz) * nn + zz * hp.w;
        hn4.w = v ? hv : hp.w;  o4.w = v ? hv : 0.f;
    }
    hr4.x = roundtf(hn4.x); hr4.y = roundtf(hn4.y);
    hr4.z = roundtf(hn4.z); hr4.w = roundtf(hn4.w);

    *reinterpret_cast<float4*>(&h[ho])  = hn4;
    *reinterpret_cast<float4*>(&hr[ho]) = hr4;
    float* op = (d == 0 ? outf : outb) + ((long)i * ROWS + t * Bb_ + b) * Hh + c4;
    *reinterpret_cast<float4*>(op) = o4;
}

// ---------------- K7: scatter + reverse + layernorm (writes rounded) ---------
__global__ void __launch_bounds__(128) k_scores_ln(
    const float* __restrict__ outf, const float* __restrict__ outb,
    const int* __restrict__ scat, const int* __restrict__ seq_len,
    const float* __restrict__ ln_g, const float* __restrict__ ln_b,
    float* __restrict__ scln)
{
    int j = blockIdx.x;          // row (t*B+b) in mask layout
    int i = blockIdx.y;          // agent
    int tid = threadIdx.x;       // 128 threads, 4 cols each
    __shared__ float s1[128], s2[128];
    float v0 = 0.f, v1 = 0.f, v2 = 0.f, v3 = 0.f;
    int k = scat[j];
    if (k >= 0) {
        int tp = k >> 10, bp = k & 1023;
        if (tid < 64) {
            float4 f = *reinterpret_cast<const float4*>(&outf[((long)i * ROWS + k) * Hh + tid * 4]);
            v0 = f.x; v1 = f.y; v2 = f.z; v3 = f.w;
        } else {
            int sl = seq_len[bp];
            if (tp < sl) {
                int rb = sl - 1 - tp;
                float4 f = *reinterpret_cast<const float4*>(
                    &outb[((long)i * ROWS + rb * Bb_ + bp) * Hh + (tid - 64) * 4]);
                v0 = f.x; v1 = f.y; v2 = f.z; v3 = f.w;
            }
        }
    }
    s1[tid] = v0 + v1 + v2 + v3;
    s2[tid] = v0 * v0 + v1 * v1 + v2 * v2 + v3 * v3;
    __syncthreads();
    for (int off = 64; off > 0; off >>= 1) {
        if (tid < off) { s1[tid] += s1[tid + off]; s2[tid] += s2[tid + off]; }
        __syncthreads();
    }
    float mu  = s1[0] * (1.f / H2);
    float var = s2[0] * (1.f / H2) - mu * mu;
    float rs  = rsqrtf(var + 1e-5f);
    int c = tid * 4;
    const float* g = &ln_g[i * H2 + c];
    const float* bt = &ln_b[i * H2 + c];
    float4 o;
    o.x = roundtf((v0 - mu) * rs * g[0] + bt[0]);
    o.y = roundtf((v1 - mu) * rs * g[1] + bt[1]);
    o.z = roundtf((v2 - mu) * rs * g[2] + bt[2]);
    o.w = roundtf((v3 - mu) * rs * g[3] + bt[3]);
    *reinterpret_cast<float4*>(&scln[((long)i * ROWS + j) * H2 + c]) = o;
}

// ---------------- K9: copy final hidden states to output ---------------------
__global__ void __launch_bounds__(256) k_copy_hx(
    const float* __restrict__ h, float* __restrict__ out, int n)
{
    int i = blockIdx.x * blockDim.x + threadIdx.x;
    if (i < n) out[i] = h[i];
}

// ---------------- host orchestration -----------------------------------------
extern "C" void kernel_launch(void* const* d_in, const int* in_sizes, int n_in,
                              void* d_out, int out_size)
{
    const float* plans         = (const float*)d_in[0];
    const float* comm_plans    = (const float*)d_in[1];
    const float* coord_hiddens = (const float*)d_in[2];
    const float* dummy_noise   = (const float*)d_in[3];
    const float* Wi_f = (const float*)d_in[4];
    const float* Wh_f = (const float*)d_in[5];
    const float* Wi_b = (const float*)d_in[6];
    const float* Wh_b = (const float*)d_in[7];
    const float* ln_g = (const float*)d_in[8];
    const float* ln_b = (const float*)d_in[9];
    const float* W1   = (const float*)d_in[10];
    const float* b1   = (const float*)d_in[11];
    const float* W2   = (const float*)d_in[12];
    const float* b2   = (const float*)d_in[13];
    float* out = (float*)d_out;

    float *xg, *gi, *gh, *outf, *outb, *scln, *part, *hst, *hr, *wit, *wht, *w1t;
    int *fwd, *bwd, *scat, *Pm, *Pp, *seq, *emp, *anyc, *anyp;
    unsigned char* mreal;
    cudaGetSymbolAddress((void**)&xg,   g_xg);
    cudaGetSymbolAddress((void**)&gi,   g_gi);
    cudaGetSymbolAddress((void**)&gh,   g_gh);
    cudaGetSymbolAddress((void**)&outf, g_outf);
    cudaGetSymbolAddress((void**)&outb, g_outb);
    cudaGetSymbolAddress((void**)&scln, g_scln);
    cudaGetSymbolAddress((void**)&part, g_part);
    cudaGetSymbolAddress((void**)&hst,  g_h);
    cudaGetSymbolAddress((void**)&hr,   g_hr);
    cudaGetSymbolAddress((void**)&wit,  g_wit);
    cudaGetSymbolAddress((void**)&wht,  g_wht);
    cudaGetSymbolAddress((void**)&w1t,  g_w1t);
    cudaGetSymbolAddress((void**)&fwd,  g_fwd);
    cudaGetSymbolAddress((void**)&bwd,  g_bwd);
    cudaGetSymbolAddress((void**)&scat, g_scat);
    cudaGetSymbolAddress((void**)&Pm,   g_Pmask);
    cudaGetSymbolAddress((void**)&Pp,   g_Ppm);
    cudaGetSymbolAddress((void**)&seq,  g_seq);
    cudaGetSymbolAddress((void**)&emp,  g_empty);
    cudaGetSymbolAddress((void**)&anyc, g_anyc);
    cudaGetSymbolAddress((void**)&anyp, g_anyp);
    cudaGetSymbolAddress((void**)&mreal, g_mreal);

    cudaFuncSetAttribute(gemm_pre, cudaFuncAttributeMaxDynamicSharedMemorySize,
                         GSMEM_BYTES);
    cudaFuncSetAttribute(gemm_mlp, cudaFuncAttributeMaxDynamicSharedMemorySize,
                         GSMEM_BYTES);

    // masks + packing indices
    k_rowflags<<<1024, 256>>>(comm_plans, plans, anyc, anyp);
    k_maskreal<<<4, 256>>>(anyc, anyp, emp, mreal);
    k_indices<<<1, 1024>>>(mreal, seq, fwd, bwd, scat, Pm, Pp);

    // init hidden + pre-round weights
    k_prep_h0<<<(NC * Bb_ * Hh + 255) / 256, 256>>>(coord_hiddens, hst, hr, NC * Bb_ * Hh);
    k_prep_wi<<<(int)(((long)NC * H3 * TP + 255) / 256), 256>>>(Wi_f, Wi_b, wit);
    k_prep_wh<<<(int)(((long)NC * H3 * Hh + 255) / 256), 256>>>(Wh_f, Wh_b, wht);
    k_prep_w1<<<(int)(((long)NA * Hh * H2 + 255) / 256), 256>>>(W1, w1t);

    // gather inputs (rounded) and input projections
    k_gather<<<dim3(ROWS / 4, NC), 256>>>(plans, comm_plans, dummy_noise, fwd, bwd, emp, xg);
    gemm_pre<<<dim3(ROWS / BM, H3 / BN, NC), 256, GSMEM_BYTES>>>(
        xg, wit, gi, nullptr,
        ROWS, H3, TP,
        (long)ROWS * TP, (long)H3 * TP, (long)ROWS * H3, 0, 0);

    // 16 recurrent steps: gh GEMM + gates
    for (int t = 0; t < NDm; t++) {
        gemm_pre<<<dim3(Bb_ / BM, H3 / BN, NC), 256, GSMEM_BYTES>>>(
            hr, wht, gh, nullptr,
            Bb_, H3, Hh,
            (long)Bb_ * Hh, (long)H3 * Hh, (long)Bb_ * H3, 0, 0);
        k_gates<<<dim3(Bb_, NC), 64>>>(gi, gh, hst, hr, outf, outb, seq, t);
    }

    // scatter + reverse + layernorm (rounded output)
    k_scores_ln<<<dim3(ROWS, NA), 128>>>(outf, outb, scat, seq, ln_g, ln_b, scln);

    // MLP + fused W2 partial dots (h1 never materialized)
    gemm_mlp<<<dim3(ROWS / BM, Hh / BN, NA), 256, GSMEM_BYTES>>>(
        scln, w1t, b1, W2, part);
    k_w2combine<<<(NA * ROWS * 2 + 255) / 256, 256>>>(part, b2, out);

    // coord_rnn_hxs (N, 2, B, H) appended after coord_masks
    int masks_elems = NA * NDm * Bb_ * 2;
    int hx_elems = NC * Bb_ * Hh;
    if (out_size >= masks_elems + hx_elems) {
        k_copy_hx<<<(hx_elems + 255) / 256, 256>>>(hst, out + masks_elems, hx_elems);
    }
}